// round 12
// baseline (speedup 1.0000x reference)
#include <cuda_runtime.h>
#include <cuda_bf16.h>
#include <math.h>
#include <stdint.h>

// ---------------- problem constants ----------------
#define NH    4
#define HD    256
#define SEQ   1024
#define BATCH 8
#define MTOK  (BATCH*SEQ)
#define FF    1024

#define WOFF_Q  0
#define WOFF_K  262144
#define WOFF_V  524288
#define WOFF_O  786432
#define WOFF_F1 1048576
#define WOFF_F2 1310720
#define WTOT    1572864

// ---------------- scratch ----------------
__device__ __align__(16) __nv_bfloat16 g_xh [(size_t)MTOK*HD];
__device__ __align__(16) __nv_bfloat16 g_xl [(size_t)MTOK*HD];
__device__ __align__(16) __nv_bfloat16 g_wh [(size_t)WTOT];
__device__ __align__(16) __nv_bfloat16 g_wl [(size_t)WTOT];
__device__ __align__(16) __nv_bfloat16 g_qh [(size_t)NH*MTOK*HD];
__device__ __align__(16) __nv_bfloat16 g_ql [(size_t)NH*MTOK*HD];
__device__ __align__(16) __nv_bfloat16 g_kh [(size_t)NH*MTOK*HD];
__device__ __align__(16) __nv_bfloat16 g_kl [(size_t)NH*MTOK*HD];
__device__ __align__(16) __nv_bfloat16 g_vh [(size_t)NH*MTOK*HD];
__device__ __align__(16) __nv_bfloat16 g_vl [(size_t)NH*MTOK*HD];
__device__ __align__(16) __nv_bfloat16 g_ath[(size_t)MTOK*NH*HD];
__device__ __align__(16) __nv_bfloat16 g_atl[(size_t)MTOK*NH*HD];
__device__ __align__(16) __nv_bfloat16 g_x1h[(size_t)MTOK*HD];
__device__ __align__(16) __nv_bfloat16 g_x1l[(size_t)MTOK*HD];
__device__ __align__(16) __nv_bfloat16 g_hh [(size_t)MTOK*FF];
__device__ __align__(16) __nv_bfloat16 g_hl [(size_t)MTOK*FF];
__device__ float g_x1 [(size_t)MTOK*HD];
__device__ float g_t1 [(size_t)MTOK*HD];

// ---------------- helpers ----------------
__device__ __forceinline__ void packsplit(float a, float b, unsigned& hi, unsigned& lo)
{
    __nv_bfloat16 ah = __float2bfloat16_rn(a);
    __nv_bfloat16 bh = __float2bfloat16_rn(b);
    __nv_bfloat162 h = __halves2bfloat162(ah, bh);
    __nv_bfloat162 l = __floats2bfloat162_rn(a - __bfloat162float(ah),
                                             b - __bfloat162float(bh));
    hi = *reinterpret_cast<unsigned*>(&h);
    lo = *reinterpret_cast<unsigned*>(&l);
}

__device__ __forceinline__ void split8(__nv_bfloat16* hi_p, __nv_bfloat16* lo_p, float4 v)
{
    unsigned h01, l01, h23, l23;
    packsplit(v.x, v.y, h01, l01);
    packsplit(v.z, v.w, h23, l23);
    *reinterpret_cast<uint2*>(hi_p) = make_uint2(h01, h23);
    *reinterpret_cast<uint2*>(lo_p) = make_uint2(l01, l23);
}

__device__ __forceinline__ void mma16816(float* c, const unsigned* a, const unsigned* b)
{
    asm volatile(
        "mma.sync.aligned.m16n8k16.row.col.f32.bf16.bf16.f32 "
        "{%0,%1,%2,%3}, {%4,%5,%6,%7}, {%8,%9}, {%0,%1,%2,%3};\n"
        : "+f"(c[0]), "+f"(c[1]), "+f"(c[2]), "+f"(c[3])
        : "r"(a[0]), "r"(a[1]), "r"(a[2]), "r"(a[3]), "r"(b[0]), "r"(b[1]));
}

__device__ __forceinline__ void ldsm4(unsigned* d, unsigned addr)
{
    asm volatile("ldmatrix.sync.aligned.m8n8.x4.shared.b16 {%0,%1,%2,%3}, [%4];"
                 : "=r"(d[0]), "=r"(d[1]), "=r"(d[2]), "=r"(d[3]) : "r"(addr));
}

__device__ __forceinline__ void ldsm4t(unsigned* d, unsigned addr)
{
    asm volatile("ldmatrix.sync.aligned.m8n8.x4.trans.shared.b16 {%0,%1,%2,%3}, [%4];"
                 : "=r"(d[0]), "=r"(d[1]), "=r"(d[2]), "=r"(d[3]) : "r"(addr));
}

__device__ __forceinline__ void cpasync16(unsigned dst, const void* src)
{
    asm volatile("cp.async.cg.shared.global [%0], [%1], 16;" :: "r"(dst), "l"(src));
}
__device__ __forceinline__ void cpcommit()
{
    asm volatile("cp.async.commit_group;" ::: "memory");
}
template<int N>
__device__ __forceinline__ void cpwait()
{
    asm volatile("cp.async.wait_group %0;" :: "n"(N) : "memory");
}

// ---------------- pre-split kernels ----------------
__global__ __launch_bounds__(256) void split_x_kernel(
    const float* __restrict__ x, __nv_bfloat16* __restrict__ oh, __nv_bfloat16* __restrict__ ol)
{
    const size_t e = ((size_t)blockIdx.x * 256 + threadIdx.x) * 4;
    if (e >= (size_t)MTOK * HD) return;
    split8(oh + e, ol + e, *(const float4*)(x + e));
}

__global__ __launch_bounds__(256) void split_w_kernel(
    const float* __restrict__ wq, const float* __restrict__ wk, const float* __restrict__ wv,
    const float* __restrict__ wo, const float* __restrict__ f1, const float* __restrict__ f2,
    __nv_bfloat16* __restrict__ oh, __nv_bfloat16* __restrict__ ol)
{
    const size_t e = ((size_t)blockIdx.x * 256 + threadIdx.x) * 4;
    if (e >= (size_t)WTOT) return;
    const float* src; size_t off;
    if      (e < WOFF_K)  { src = wq; off = WOFF_Q;  }
    else if (e < WOFF_V)  { src = wk; off = WOFF_K;  }
    else if (e < WOFF_O)  { src = wv; off = WOFF_V;  }
    else if (e < WOFF_F1) { src = wo; off = WOFF_O;  }
    else if (e < WOFF_F2) { src = f1; off = WOFF_F1; }
    else                  { src = f2; off = WOFF_F2; }
    split8(oh + e, ol + e, *(const float4*)(src + (e - off)));
}

// =================================================================
// bf16x3 GEMM v2: cp.async + ldmatrix, 2 CTAs/SM, interleaved mma.
// =================================================================
#define ASTR 40
#define BOFF (2*2*128*ASTR)
#define GEMM_SMEM (2*2*128*ASTR*2*2)

template<int MODE>
__device__ __forceinline__ void gemm_core(
    const __nv_bfloat16* __restrict__ Ah, const __nv_bfloat16* __restrict__ Al,
    const __nv_bfloat16* __restrict__ Bh, const __nv_bfloat16* __restrict__ Bl,
    const float* __restrict__ bias, float* __restrict__ C,
    __nv_bfloat16* __restrict__ Chi, __nv_bfloat16* __restrict__ Clo,
    int N, int K, int m0, int n0)
{
    extern __shared__ __nv_bfloat16 sm_bf[];
    const unsigned sbase = (unsigned)__cvta_generic_to_shared(sm_bf);

    const int tid  = threadIdx.x;
    const int lane = tid & 31, warp = tid >> 5;
    const int wm = (warp >> 2) << 6;
    const int wn = (warp & 3)  << 5;
    const int g = lane >> 2, t = lane & 3;
    const int KT = K >> 5;

    const __nv_bfloat16* Agh = Ah + (size_t)m0 * K;
    const __nv_bfloat16* Agl = Al + (size_t)m0 * K;
    const __nv_bfloat16* Bgh = Bh + (size_t)n0 * K;
    const __nv_bfloat16* Bgl = Bl + (size_t)n0 * K;

    const int sr = tid >> 2;
    const int scol = (tid & 3) << 3;

    float acc[4][4][4];
    #pragma unroll
    for (int i = 0; i < 4; i++)
        #pragma unroll
        for (int j = 0; j < 4; j++)
            #pragma unroll
            for (int q = 0; q < 4; q++) acc[i][j][q] = 0.f;

    const int arow = lane & 15;
    const int acol = (lane >> 4) << 3;
    const int brow = (lane & 7) | ((lane >> 1) & 8);
    const int bcol = lane & 8;

    {
        #pragma unroll
        for (int i = 0; i < 2; i++) {
            const int r = (i << 6) + sr;
            const unsigned d0 = sbase + (unsigned)(((0*2 + 0)*128 + r)*ASTR + scol) * 2;
            const unsigned d1 = sbase + (unsigned)(((0*2 + 1)*128 + r)*ASTR + scol) * 2;
            const unsigned d2 = sbase + (unsigned)((BOFF + ((0*2 + 0)*128 + r)*ASTR + scol)) * 2;
            const unsigned d3 = sbase + (unsigned)((BOFF + ((0*2 + 1)*128 + r)*ASTR + scol)) * 2;
            cpasync16(d0, Agh + (size_t)r * K + scol);
            cpasync16(d1, Agl + (size_t)r * K + scol);
            cpasync16(d2, Bgh + (size_t)r * K + scol);
            cpasync16(d3, Bgl + (size_t)r * K + scol);
        }
        cpcommit();
    }

    for (int kt = 0; kt < KT; kt++) {
        const int buf = kt & 1;
        if (kt + 1 < KT) {
            const int ko = (kt + 1) << 5;
            const int nb = buf ^ 1;
            #pragma unroll
            for (int i = 0; i < 2; i++) {
                const int r = (i << 6) + sr;
                const unsigned d0 = sbase + (unsigned)(((nb*2 + 0)*128 + r)*ASTR + scol) * 2;
                const unsigned d1 = sbase + (unsigned)(((nb*2 + 1)*128 + r)*ASTR + scol) * 2;
                const unsigned d2 = sbase + (unsigned)((BOFF + ((nb*2 + 0)*128 + r)*ASTR + scol)) * 2;
                const unsigned d3 = sbase + (unsigned)((BOFF + ((nb*2 + 1)*128 + r)*ASTR + scol)) * 2;
                cpasync16(d0, Agh + (size_t)r * K + ko + scol);
                cpasync16(d1, Agl + (size_t)r * K + ko + scol);
                cpasync16(d2, Bgh + (size_t)r * K + ko + scol);
                cpasync16(d3, Bgl + (size_t)r * K + ko + scol);
            }
            cpcommit();
            cpwait<1>();
        } else {
            cpwait<0>();
        }
        __syncthreads();

        const unsigned aHi = sbase + (unsigned)((buf*2 + 0)*128*ASTR) * 2;
        const unsigned aLo = sbase + (unsigned)((buf*2 + 1)*128*ASTR) * 2;
        const unsigned bHi = sbase + (unsigned)((BOFF + (buf*2 + 0)*128*ASTR)) * 2;
        const unsigned bLo = sbase + (unsigned)((BOFF + (buf*2 + 1)*128*ASTR)) * 2;

        #pragma unroll
        for (int ks = 0; ks < 2; ks++) {
            const int kc = ks << 4;
            unsigned bh[2][4], bl[2][4];
            #pragma unroll
            for (int np = 0; np < 2; np++) {
                const unsigned bo = (unsigned)((wn + (np << 4) + brow)*ASTR + kc + bcol) * 2;
                ldsm4(bh[np], bHi + bo);
                ldsm4(bl[np], bLo + bo);
            }
            #pragma unroll
            for (int mh = 0; mh < 2; mh++) {
                unsigned ah[2][4], al[2][4];
                #pragma unroll
                for (int m2 = 0; m2 < 2; m2++) {
                    const unsigned ao = (unsigned)((wm + ((mh*2 + m2) << 4) + arow)*ASTR + kc + acol) * 2;
                    ldsm4(ah[m2], aHi + ao);
                    ldsm4(al[m2], aLo + ao);
                }
                // interleaved: per-accumulator order (hh, hl, lh) preserved
                #pragma unroll
                for (int m2 = 0; m2 < 2; m2++) {
                    #pragma unroll
                    for (int nt = 0; nt < 4; nt++)
                        mma16816(acc[mh*2 + m2][nt], ah[m2], bh[nt >> 1] + ((nt & 1) << 1));
                    #pragma unroll
                    for (int nt = 0; nt < 4; nt++)
                        mma16816(acc[mh*2 + m2][nt], ah[m2], bl[nt >> 1] + ((nt & 1) << 1));
                    #pragma unroll
                    for (int nt = 0; nt < 4; nt++)
                        mma16816(acc[mh*2 + m2][nt], al[m2], bh[nt >> 1] + ((nt & 1) << 1));
                }
            }
        }
        __syncthreads();
    }

    #pragma unroll
    for (int mt = 0; mt < 4; mt++) {
        const int row = m0 + wm + (mt << 4) + g;
        #pragma unroll
        for (int nt = 0; nt < 4; nt++) {
            const int col = n0 + wn + (nt << 3) + (t << 1);
            float bx = 0.f, by = 0.f;
            if (bias) { bx = bias[col]; by = bias[col + 1]; }
            float v0 = acc[mt][nt][0] + bx, v1 = acc[mt][nt][1] + by;
            float v2 = acc[mt][nt][2] + bx, v3 = acc[mt][nt][3] + by;
            if (MODE & 1) {
                v0 = fmaxf(v0, 0.f); v1 = fmaxf(v1, 0.f);
                v2 = fmaxf(v2, 0.f); v3 = fmaxf(v3, 0.f);
            }
            if (MODE & 2) {
                unsigned h01, l01, h23, l23;
                packsplit(v0, v1, h01, l01);
                packsplit(v2, v3, h23, l23);
                *(unsigned*)(Chi + (size_t)row * N + col)       = h01;
                *(unsigned*)(Clo + (size_t)row * N + col)       = l01;
                *(unsigned*)(Chi + (size_t)(row + 8) * N + col) = h23;
                *(unsigned*)(Clo + (size_t)(row + 8) * N + col) = l23;
            } else {
                *(float2*)(C + (size_t)row * N + col)       = make_float2(v0, v1);
                *(float2*)(C + (size_t)(row + 8) * N + col) = make_float2(v2, v3);
            }
        }
    }
}

template<int MODE>
__global__ __launch_bounds__(256, 2) void gemm_kernel(
    const __nv_bfloat16* __restrict__ Ah, const __nv_bfloat16* __restrict__ Al,
    const __nv_bfloat16* __restrict__ Bh, const __nv_bfloat16* __restrict__ Bl,
    const float* __restrict__ bias, float* __restrict__ C,
    __nv_bfloat16* __restrict__ Chi, __nv_bfloat16* __restrict__ Clo, int N, int K)
{
    gemm_core<MODE>(Ah, Al, Bh, Bl, bias, C, Chi, Clo, N, K,
                    blockIdx.y << 7, blockIdx.x << 7);
}

__global__ __launch_bounds__(256, 2) void gemm_qkv_kernel(
    const __nv_bfloat16* __restrict__ xh, const __nv_bfloat16* __restrict__ xl,
    const __nv_bfloat16* __restrict__ wh, const __nv_bfloat16* __restrict__ wl,
    __nv_bfloat16* __restrict__ qh, __nv_bfloat16* __restrict__ ql,
    __nv_bfloat16* __restrict__ kh, __nv_bfloat16* __restrict__ kl,
    __nv_bfloat16* __restrict__ vh, __nv_bfloat16* __restrict__ vl)
{
    const int z = blockIdx.z;
    const int mat = z >> 2, h = z & 3;
    const size_t woff = (size_t)mat * 262144 + (size_t)h * 65536;
    __nv_bfloat16* Chi = (mat == 0 ? qh : mat == 1 ? kh : vh) + (size_t)h * MTOK * HD;
    __nv_bfloat16* Clo = (mat == 0 ? ql : mat == 1 ? kl : vl) + (size_t)h * MTOK * HD;
    gemm_core<2>(xh, xl, wh + woff, wl + woff, nullptr, nullptr, Chi, Clo, HD, HD,
                 blockIdx.y << 7, blockIdx.x << 7);
}

// =================================================================
// flash v6: 128 q-rows/CTA, 16-key K/V tiles DOUBLE-BUFFERED
// (cp.async prefetch overlaps compute), interleaved mma,
// warp-uniform rescale skip. 8 warps, 16 rows each.
// =================================================================
#define QS 264
#define FQL (128*QS)
#define FK  (2*128*QS)              // [buf][split][16*QS]
#define FV  (FK + 4*16*QS)
#define KTILE (16*QS)
#define FLASH_SMEM ((2*128*QS + 8*16*QS)*2)   // 202752 B
#define L2E 1.4426950408889634f

__global__ __launch_bounds__(256, 1) void flash_mma_kernel(
    const __nv_bfloat16* __restrict__ qh, const __nv_bfloat16* __restrict__ ql,
    const __nv_bfloat16* __restrict__ kh, const __nv_bfloat16* __restrict__ kl,
    const __nv_bfloat16* __restrict__ vh, const __nv_bfloat16* __restrict__ vl,
    const int* __restrict__ amask,
    __nv_bfloat16* __restrict__ atth, __nv_bfloat16* __restrict__ attl)
{
    extern __shared__ __nv_bfloat16 sm[];
    __shared__ int sMq[128];
    __shared__ int sMk[2][16];

    const int tid  = threadIdx.x;
    const int lane = tid & 31, w = tid >> 5;
    const int g = lane >> 2, t = lane & 3;
    const int bh = blockIdx.y;
    const int b = bh >> 2, h = bh & 3;
    const int qidx = (int)gridDim.x - 1 - (int)blockIdx.x;   // heavy first
    const int m0 = qidx << 7;
    const size_t base = ((size_t)h * MTOK + (size_t)b * SEQ) * HD;

    const unsigned sb = (unsigned)__cvta_generic_to_shared(sm);
    const unsigned bQh = sb;
    const unsigned bQl = sb + FQL*2;

    const unsigned offA = (((w << 4) + (lane & 15)) * QS + ((lane >> 4) << 3)) * 2;
    const unsigned offB = ((((lane & 7) | ((lane >> 1) & 8)) * QS) + (lane & 8)) * 2;
    const unsigned offV = (((lane & 15) * QS) + ((lane >> 4) << 3)) * 2;

    // per-thread KV staging coords: r = tid>>4 (0..15), c = (tid&15)*16 elems? No:
    // 16 rows x 256 cols = 4096 elems = 512 x 8-elem chunks; 256 thr -> 2 chunks per array
    const int kr = tid >> 4;             // 0..15
    const int kc = (tid & 15) << 4;      // 0,16,...,240 (two 8-elem chunks)

    // ---- prologue: Q + KV[0] + masks, one commit group ----
    {
        const __nv_bfloat16* Qh = qh + base + (size_t)m0 * HD;
        const __nv_bfloat16* Ql = ql + base + (size_t)m0 * HD;
        for (int i = tid; i < 4096; i += 256) {
            int r = i >> 5, c = (i & 31) << 3;
            cpasync16(bQh + (unsigned)(r*QS + c)*2, Qh + (size_t)r*HD + c);
            cpasync16(bQl + (unsigned)(r*QS + c)*2, Ql + (size_t)r*HD + c);
        }
        const __nv_bfloat16* Kh = kh + base;
        const __nv_bfloat16* Kl = kl + base;
        const __nv_bfloat16* Vh = vh + base;
        const __nv_bfloat16* Vl = vl + base;
        const size_t go = (size_t)kr * HD + kc;
        const unsigned so = (unsigned)(kr*QS + kc) * 2;
        cpasync16(sb + (FK + 0*KTILE)*2 + so,      Kh + go);
        cpasync16(sb + (FK + 0*KTILE)*2 + so + 16, Kh + go + 8);
        cpasync16(sb + (FK + 1*KTILE)*2 + so,      Kl + go);
        cpasync16(sb + (FK + 1*KTILE)*2 + so + 16, Kl + go + 8);
        cpasync16(sb + (FV + 0*KTILE)*2 + so,      Vh + go);
        cpasync16(sb + (FV + 0*KTILE)*2 + so + 16, Vh + go + 8);
        cpasync16(sb + (FV + 1*KTILE)*2 + so,      Vl + go);
        cpasync16(sb + (FV + 1*KTILE)*2 + so + 16, Vl + go + 8);
        cpcommit();
        if (tid < 128) sMq[tid] = amask[b * SEQ + m0 + tid];
        if (tid < 16)  sMk[0][tid] = amask[b * SEQ + tid];
    }

    float accO[32][4];
    #pragma unroll
    for (int i = 0; i < 32; i++)
        #pragma unroll
        for (int j = 0; j < 4; j++) accO[i][j] = 0.f;
    float m_run0 = -1e30f, m_run1 = -1e30f, l_run0 = 0.f, l_run1 = 0.f;

    const int gi0 = m0 + (w << 4) + g;
    const int gi1 = gi0 + 8;

    const int ntiles = (qidx + 1) << 3;
    for (int kt = 0; kt < ntiles; kt++) {
        const int buf = kt & 1;
        const int j0 = kt << 4;
        if (kt + 1 < ntiles) {
            const int nb = buf ^ 1;
            const int j1 = (kt + 1) << 4;
            const __nv_bfloat16* Kh = kh + base + (size_t)j1 * HD;
            const __nv_bfloat16* Kl = kl + base + (size_t)j1 * HD;
            const __nv_bfloat16* Vh = vh + base + (size_t)j1 * HD;
            const __nv_bfloat16* Vl = vl + base + (size_t)j1 * HD;
            const size_t go = (size_t)kr * HD + kc;
            const unsigned so = (unsigned)(kr*QS + kc) * 2;
            cpasync16(sb + (FK + (nb*2 + 0)*KTILE)*2 + so,      Kh + go);
            cpasync16(sb + (FK + (nb*2 + 0)*KTILE)*2 + so + 16, Kh + go + 8);
            cpasync16(sb + (FK + (nb*2 + 1)*KTILE)*2 + so,      Kl + go);
            cpasync16(sb + (FK + (nb*2 + 1)*KTILE)*2 + so + 16, Kl + go + 8);
            cpasync16(sb + (FV + (nb*2 + 0)*KTILE)*2 + so,      Vh + go);
            cpasync16(sb + (FV + (nb*2 + 0)*KTILE)*2 + so + 16, Vh + go + 8);
            cpasync16(sb + (FV + (nb*2 + 1)*KTILE)*2 + so,      Vl + go);
            cpasync16(sb + (FV + (nb*2 + 1)*KTILE)*2 + so + 16, Vl + go + 8);
            cpcommit();
            if (tid < 16) sMk[nb][tid] = amask[b * SEQ + j1 + tid];
            cpwait<1>();
        } else {
            cpwait<0>();
        }
        __syncthreads();

        const unsigned bKh = sb + (FK + (buf*2 + 0)*KTILE)*2;
        const unsigned bKl = sb + (FK + (buf*2 + 1)*KTILE)*2;
        const unsigned bVh = sb + (FV + (buf*2 + 0)*KTILE)*2;
        const unsigned bVl = sb + (FV + (buf*2 + 1)*KTILE)*2;

        // ---- scores: 16 rows x 16 keys per warp ----
        float sc[2][4];
        #pragma unroll
        for (int i = 0; i < 2; i++)
            #pragma unroll
            for (int j = 0; j < 4; j++) sc[i][j] = 0.f;

        #pragma unroll 4
        for (int ks = 0; ks < 16; ks++) {
            unsigned aqh[4], aql[4], kbh[4], kbl[4];
            ldsm4(aqh, bQh + offA + ks*32);
            ldsm4(aql, bQl + offA + ks*32);
            ldsm4(kbh, bKh + offB + ks*32);
            ldsm4(kbl, bKl + offB + ks*32);
            mma16816(sc[0], aqh, kbh);
            mma16816(sc[1], aqh, kbh+2);
            mma16816(sc[0], aqh, kbl);
            mma16816(sc[1], aqh, kbl+2);
            mma16816(sc[0], aql, kbh);
            mma16816(sc[1], aql, kbh+2);
        }

        // ---- mask + online softmax ----
        const int qm0 = sMq[(w << 4) + g];
        const int qm1 = sMq[(w << 4) + g + 8];
        float mx0 = -1e30f, mx1 = -1e30f;
        #pragma unroll
        for (int nt = 0; nt < 2; nt++) {
            const int jb = (nt << 3) + (t << 1);
            const int k0 = sMk[buf][jb], k1 = sMk[buf][jb + 1];
            const int gj0 = j0 + jb, gj1 = gj0 + 1;
            sc[nt][0] = (qm0 && k0 && gj0 <= gi0) ? sc[nt][0] * 0.0625f : -1e30f;
            sc[nt][1] = (qm0 && k1 && gj1 <= gi0) ? sc[nt][1] * 0.0625f : -1e30f;
            sc[nt][2] = (qm1 && k0 && gj0 <= gi1) ? sc[nt][2] * 0.0625f : -1e30f;
            sc[nt][3] = (qm1 && k1 && gj1 <= gi1) ? sc[nt][3] * 0.0625f : -1e30f;
            mx0 = fmaxf(mx0, fmaxf(sc[nt][0], sc[nt][1]));
            mx1 = fmaxf(mx1, fmaxf(sc[nt][2], sc[nt][3]));
        }
        mx0 = fmaxf(mx0, __shfl_xor_sync(0xffffffffu, mx0, 1, 4));
        mx0 = fmaxf(mx0, __shfl_xor_sync(0xffffffffu, mx0, 2, 4));
        mx1 = fmaxf(mx1, __shfl_xor_sync(0xffffffffu, mx1, 1, 4));
        mx1 = fmaxf(mx1, __shfl_xor_sync(0xffffffffu, mx1, 2, 4));

        const float mn0 = fmaxf(m_run0, mx0);
        const float mn1 = fmaxf(m_run1, mx1);
        const float al0 = exp2f((m_run0 - mn0) * L2E);
        const float al1 = exp2f((m_run1 - mn1) * L2E);
        m_run0 = mn0; m_run1 = mn1;

        float ps0 = 0.f, ps1 = 0.f;
        #pragma unroll
        for (int nt = 0; nt < 2; nt++) {
            float p0 = exp2f((sc[nt][0] - mn0) * L2E);
            float p1 = exp2f((sc[nt][1] - mn0) * L2E);
            float p2 = exp2f((sc[nt][2] - mn1) * L2E);
            float p3 = exp2f((sc[nt][3] - mn1) * L2E);
            sc[nt][0] = p0; sc[nt][1] = p1; sc[nt][2] = p2; sc[nt][3] = p3;
            ps0 += p0 + p1; ps1 += p2 + p3;
        }
        ps0 += __shfl_xor_sync(0xffffffffu, ps0, 1, 4);
        ps0 += __shfl_xor_sync(0xffffffffu, ps0, 2, 4);
        ps1 += __shfl_xor_sync(0xffffffffu, ps1, 1, 4);
        ps1 += __shfl_xor_sync(0xffffffffu, ps1, 2, 4);
        l_run0 = l_run0 * al0 + ps0;
        l_run1 = l_run1 * al1 + ps1;

        // warp-uniform skip of identity rescale
        const bool skip = __all_sync(0xffffffffu, (al0 == 1.f) && (al1 == 1.f));
        if (!skip) {
            #pragma unroll
            for (int i = 0; i < 32; i++) {
                accO[i][0] *= al0; accO[i][1] *= al0;
                accO[i][2] *= al1; accO[i][3] *= al1;
            }
        }

        // ---- O += P * V (16 keys x 256 dims), interleaved ----
        {
            unsigned aPh[4], aPl[4];
            packsplit(sc[0][0], sc[0][1], aPh[0], aPl[0]);
            packsplit(sc[0][2], sc[0][3], aPh[1], aPl[1]);
            packsplit(sc[1][0], sc[1][1], aPh[2], aPl[2]);
            packsplit(sc[1][2], sc[1][3], aPh[3], aPl[3]);
            #pragma unroll
            for (int nv = 0; nv < 16; nv++) {
                unsigned vbh[4], vbl[4];
                ldsm4t(vbh, bVh + offV + nv*32);
                ldsm4t(vbl, bVl + offV + nv*32);
                mma16816(accO[2*nv],   aPh, vbh);
                mma16816(accO[2*nv+1], aPh, vbh+2);
                mma16816(accO[2*nv],   aPh, vbl);
                mma16816(accO[2*nv+1], aPh, vbl+2);
                mma16816(accO[2*nv],   aPl, vbh);
                mma16816(accO[2*nv+1], aPl, vbh+2);
            }
        }
        __syncthreads();
    }

    // ---- epilogue ----
    const int qm0 = sMq[(w << 4) + g];
    const int qm1 = sMq[(w << 4) + g + 8];
    const float inv0 = (qm0 && l_run0 > 0.f) ? (1.f / l_run0) : 0.f;
    const float inv1 = (qm1 && l_run1 > 0.f) ? (1.f / l_run1) : 0.f;
    const size_t o0 = (size_t)(b * SEQ + gi0) * (NH * HD) + h * HD;
    const size_t o1 = (size_t)(b * SEQ + gi1) * (NH * HD) + h * HD;
    #pragma unroll
    for (int nt = 0; nt < 32; nt++) {
        const int col = (nt << 3) + (t << 1);
        unsigned h0, l0, h1, l1;
        packsplit(accO[nt][0] * inv0, accO[nt][1] * inv0, h0, l0);
        packsplit(accO[nt][2] * inv1, accO[nt][3] * inv1, h1, l1);
        *(unsigned*)(atth + o0 + col) = h0;
        *(unsigned*)(attl + o0 + col) = l0;
        *(unsigned*)(atth + o1 + col) = h1;
        *(unsigned*)(attl + o1 + col) = l1;
    }
}

// ---------------- fused residual-add + LayerNorm ----------------
template<int SPLIT>
__global__ __launch_bounds__(256) void add_ln_kernel(
    const float* __restrict__ a, const float* __restrict__ b2,
    const float* __restrict__ g, const float* __restrict__ be,
    float* __restrict__ out,
    __nv_bfloat16* __restrict__ oh, __nv_bfloat16* __restrict__ ol)
{
    __shared__ float red[16];
    const int row = blockIdx.x, t = threadIdx.x;
    const size_t off = (size_t)row * HD + t;
    const float v = a[off] + b2[off];
    float sv = v, sq = v * v;
    #pragma unroll
    for (int o = 16; o; o >>= 1) {
        sv += __shfl_xor_sync(0xffffffffu, sv, o);
        sq += __shfl_xor_sync(0xffffffffu, sq, o);
    }
    if ((t & 31) == 0) { red[t >> 5] = sv; red[8 + (t >> 5)] = sq; }
    __syncthreads();
    if (t == 0) {
        float s1 = 0.f, s2 = 0.f;
        #pragma unroll
        for (int i = 0; i < 8; i++) { s1 += red[i]; s2 += red[8 + i]; }
        red[0] = s1; red[8] = s2;
    }
    __syncthreads();
    const float mu  = red[0] * (1.f / 256.f);
    const float var = red[8] * (1.f / 256.f) - mu * mu;
    const float r = (v - mu) * rsqrtf(var + 1e-5f) * g[t] + be[t];
    out[off] = r;
    if (SPLIT) {
        __nv_bfloat16 hi = __float2bfloat16_rn(r);
        oh[off] = hi;
        ol[off] = __float2bfloat16_rn(r - __bfloat162float(hi));
    }
}

// ---------------- launch ----------------
extern "C" void kernel_launch(void* const* d_in, const int* in_sizes, int n_in,
                              void* d_out, int out_size)
{
    const float* x    = (const float*)d_in[0];
    const int*   am   = (const int*  )d_in[1];
    const float* wq   = (const float*)d_in[2];
    const float* wk   = (const float*)d_in[3];
    const float* wv   = (const float*)d_in[4];
    const float* wo_w = (const float*)d_in[5];
    const float* wo_b = (const float*)d_in[6];
    const float* ln1g = (const float*)d_in[7];
    const float* ln1b = (const float*)d_in[8];
    const float* f1w  = (const float*)d_in[9];
    const float* f1b  = (const float*)d_in[10];
    const float* f2w  = (const float*)d_in[11];
    const float* f2b  = (const float*)d_in[12];
    const float* ln2g = (const float*)d_in[13];
    const float* ln2b = (const float*)d_in[14];
    float* out = (float*)d_out;
    (void)in_sizes; (void)n_in; (void)out_size;

    __nv_bfloat16 *pxh, *pxl, *pwh, *pwl, *pqh, *pql, *pkh, *pkl, *pvh, *pvl;
    __nv_bfloat16 *path, *patl, *px1h, *px1l, *phh, *phl;
    float *px1, *pt1;
    cudaGetSymbolAddress((void**)&pxh, g_xh);
    cudaGetSymbolAddress((void**)&pxl, g_xl);
    cudaGetSymbolAddress((void**)&pwh, g_wh);
    cudaGetSymbolAddress((void**)&pwl, g_wl);
    cudaGetSymbolAddress((void**)&pqh, g_qh);
    cudaGetSymbolAddress((void**)&pql, g_ql);
    cudaGetSymbolAddress((void**)&pkh, g_kh);
    cudaGetSymbolAddress((void**)&pkl, g_kl);
    cudaGetSymbolAddress((void**)&pvh, g_vh);
    cudaGetSymbolAddress((void**)&pvl, g_vl);
    cudaGetSymbolAddress((void**)&path, g_ath);
    cudaGetSymbolAddress((void**)&patl, g_atl);
    cudaGetSymbolAddress((void**)&px1h, g_x1h);
    cudaGetSymbolAddress((void**)&px1l, g_x1l);
    cudaGetSymbolAddress((void**)&phh, g_hh);
    cudaGetSymbolAddress((void**)&phl, g_hl);
    cudaGetSymbolAddress((void**)&px1, g_x1);
    cudaGetSymbolAddress((void**)&pt1, g_t1);

    cudaFuncSetAttribute(gemm_qkv_kernel, cudaFuncAttributeMaxDynamicSharedMemorySize, GEMM_SMEM);
    cudaFuncSetAttribute(gemm_kernel<0>,  cudaFuncAttributeMaxDynamicSharedMemorySize, GEMM_SMEM);
    cudaFuncSetAttribute(gemm_kernel<3>,  cudaFuncAttributeMaxDynamicSharedMemorySize, GEMM_SMEM);
    cudaFuncSetAttribute(flash_mma_kernel, cudaFuncAttributeMaxDynamicSharedMemorySize, FLASH_SMEM);

    // ---- pre-split x and weights ----
    split_x_kernel<<<MTOK*HD/1024, 256>>>(x, pxh, pxl);
    split_w_kernel<<<WTOT/1024, 256>>>(wq, wk, wv, wo_w, f1w, f2w, pwh, pwl);

    // ---- QKV projections ----
    gemm_qkv_kernel<<<dim3(HD/128, MTOK/128, 12), 256, GEMM_SMEM>>>(
        pxh, pxl, pwh, pwl, pqh, pql, pkh, pkl, pvh, pvl);

    // ---- causal flash attention (v6: double-buffered 16-key tiles) ----
    flash_mma_kernel<<<dim3(SEQ/128, BATCH*NH), 256, FLASH_SMEM>>>(
        pqh, pql, pkh, pkl, pvh, pvl, am, path, patl);

    // ---- output projection + residual/LN1 ----
    gemm_kernel<0><<<dim3(HD/128, MTOK/128), 256, GEMM_SMEM>>>(
        path, patl, pwh + WOFF_O, pwl + WOFF_O, wo_b, pt1, nullptr, nullptr, HD, NH*HD);
    add_ln_kernel<1><<<MTOK, 256>>>(x, pt1, ln1g, ln1b, px1, px1h, px1l);

    // ---- FFN ----
    gemm_kernel<3><<<dim3(FF/128, MTOK/128), 256, GEMM_SMEM>>>(
        px1h, px1l, pwh + WOFF_F1, pwl + WOFF_F1, f1b, nullptr, phh, phl, FF, HD);
    gemm_kernel<0><<<dim3(HD/128, MTOK/128), 256, GEMM_SMEM>>>(
        phh, phl, pwh + WOFF_F2, pwl + WOFF_F2, f2b, pt1, nullptr, nullptr, HD, FF);
    add_ln_kernel<0><<<MTOK, 256>>>(px1, pt1, ln2g, ln2b, out, nullptr, nullptr);
}

// round 13
// speedup vs baseline: 1.0749x; 1.0749x over previous
#include <cuda_runtime.h>
#include <cuda_bf16.h>
#include <math.h>
#include <stdint.h>

// ---------------- problem constants ----------------
#define NH    4
#define HD    256
#define SEQ   1024
#define BATCH 8
#define MTOK  (BATCH*SEQ)
#define FF    1024

#define WOFF_Q  0
#define WOFF_K  262144
#define WOFF_V  524288
#define WOFF_O  786432
#define WOFF_F1 1048576
#define WOFF_F2 1310720
#define WTOT    1572864

// ---------------- scratch ----------------
__device__ __align__(16) __nv_bfloat16 g_xh [(size_t)MTOK*HD];
__device__ __align__(16) __nv_bfloat16 g_xl [(size_t)MTOK*HD];
__device__ __align__(16) __nv_bfloat16 g_wh [(size_t)WTOT];
__device__ __align__(16) __nv_bfloat16 g_wl [(size_t)WTOT];
__device__ __align__(16) __nv_bfloat16 g_qh [(size_t)NH*MTOK*HD];
__device__ __align__(16) __nv_bfloat16 g_ql [(size_t)NH*MTOK*HD];
__device__ __align__(16) __nv_bfloat16 g_kh [(size_t)NH*MTOK*HD];
__device__ __align__(16) __nv_bfloat16 g_kl [(size_t)NH*MTOK*HD];
__device__ __align__(16) __nv_bfloat16 g_vh [(size_t)NH*MTOK*HD];
__device__ __align__(16) __nv_bfloat16 g_vl [(size_t)NH*MTOK*HD];
__device__ __align__(16) __nv_bfloat16 g_ath[(size_t)MTOK*NH*HD];
__device__ __align__(16) __nv_bfloat16 g_atl[(size_t)MTOK*NH*HD];
__device__ __align__(16) __nv_bfloat16 g_x1h[(size_t)MTOK*HD];
__device__ __align__(16) __nv_bfloat16 g_x1l[(size_t)MTOK*HD];
__device__ __align__(16) __nv_bfloat16 g_hh [(size_t)MTOK*FF];
__device__ __align__(16) __nv_bfloat16 g_hl [(size_t)MTOK*FF];
__device__ float g_x1 [(size_t)MTOK*HD];
__device__ float g_t1 [(size_t)MTOK*HD];

// ---------------- helpers ----------------
__device__ __forceinline__ void packsplit(float a, float b, unsigned& hi, unsigned& lo)
{
    __nv_bfloat16 ah = __float2bfloat16_rn(a);
    __nv_bfloat16 bh = __float2bfloat16_rn(b);
    __nv_bfloat162 h = __halves2bfloat162(ah, bh);
    __nv_bfloat162 l = __floats2bfloat162_rn(a - __bfloat162float(ah),
                                             b - __bfloat162float(bh));
    hi = *reinterpret_cast<unsigned*>(&h);
    lo = *reinterpret_cast<unsigned*>(&l);
}

__device__ __forceinline__ void split8(__nv_bfloat16* hi_p, __nv_bfloat16* lo_p, float4 v)
{
    unsigned h01, l01, h23, l23;
    packsplit(v.x, v.y, h01, l01);
    packsplit(v.z, v.w, h23, l23);
    *reinterpret_cast<uint2*>(hi_p) = make_uint2(h01, h23);
    *reinterpret_cast<uint2*>(lo_p) = make_uint2(l01, l23);
}

__device__ __forceinline__ void mma16816(float* c, const unsigned* a, const unsigned* b)
{
    asm volatile(
        "mma.sync.aligned.m16n8k16.row.col.f32.bf16.bf16.f32 "
        "{%0,%1,%2,%3}, {%4,%5,%6,%7}, {%8,%9}, {%0,%1,%2,%3};\n"
        : "+f"(c[0]), "+f"(c[1]), "+f"(c[2]), "+f"(c[3])
        : "r"(a[0]), "r"(a[1]), "r"(a[2]), "r"(a[3]), "r"(b[0]), "r"(b[1]));
}

__device__ __forceinline__ void ldsm4(unsigned* d, unsigned addr)
{
    asm volatile("ldmatrix.sync.aligned.m8n8.x4.shared.b16 {%0,%1,%2,%3}, [%4];"
                 : "=r"(d[0]), "=r"(d[1]), "=r"(d[2]), "=r"(d[3]) : "r"(addr));
}

__device__ __forceinline__ void ldsm4t(unsigned* d, unsigned addr)
{
    asm volatile("ldmatrix.sync.aligned.m8n8.x4.trans.shared.b16 {%0,%1,%2,%3}, [%4];"
                 : "=r"(d[0]), "=r"(d[1]), "=r"(d[2]), "=r"(d[3]) : "r"(addr));
}

__device__ __forceinline__ void cpasync16(unsigned dst, const void* src)
{
    asm volatile("cp.async.cg.shared.global [%0], [%1], 16;" :: "r"(dst), "l"(src));
}
__device__ __forceinline__ void cpcommit()
{
    asm volatile("cp.async.commit_group;" ::: "memory");
}
template<int N>
__device__ __forceinline__ void cpwait()
{
    asm volatile("cp.async.wait_group %0;" :: "n"(N) : "memory");
}

// ---------------- pre-split kernels ----------------
__global__ __launch_bounds__(256) void split_x_kernel(
    const float* __restrict__ x, __nv_bfloat16* __restrict__ oh, __nv_bfloat16* __restrict__ ol)
{
    const size_t e = ((size_t)blockIdx.x * 256 + threadIdx.x) * 4;
    if (e >= (size_t)MTOK * HD) return;
    split8(oh + e, ol + e, *(const float4*)(x + e));
}

__global__ __launch_bounds__(256) void split_w_kernel(
    const float* __restrict__ wq, const float* __restrict__ wk, const float* __restrict__ wv,
    const float* __restrict__ wo, const float* __restrict__ f1, const float* __restrict__ f2,
    __nv_bfloat16* __restrict__ oh, __nv_bfloat16* __restrict__ ol)
{
    const size_t e = ((size_t)blockIdx.x * 256 + threadIdx.x) * 4;
    if (e >= (size_t)WTOT) return;
    const float* src; size_t off;
    if      (e < WOFF_K)  { src = wq; off = WOFF_Q;  }
    else if (e < WOFF_V)  { src = wk; off = WOFF_K;  }
    else if (e < WOFF_O)  { src = wv; off = WOFF_V;  }
    else if (e < WOFF_F1) { src = wo; off = WOFF_O;  }
    else if (e < WOFF_F2) { src = f1; off = WOFF_F1; }
    else                  { src = f2; off = WOFF_F2; }
    split8(oh + e, ol + e, *(const float4*)(src + (e - off)));
}

// =================================================================
// bf16x3 GEMM v2: cp.async + ldmatrix, 2 CTAs/SM, interleaved mma.
// =================================================================
#define ASTR 40
#define BOFF (2*2*128*ASTR)
#define GEMM_SMEM (2*2*128*ASTR*2*2)

template<int MODE>
__device__ __forceinline__ void gemm_core(
    const __nv_bfloat16* __restrict__ Ah, const __nv_bfloat16* __restrict__ Al,
    const __nv_bfloat16* __restrict__ Bh, const __nv_bfloat16* __restrict__ Bl,
    const float* __restrict__ bias, float* __restrict__ C,
    __nv_bfloat16* __restrict__ Chi, __nv_bfloat16* __restrict__ Clo,
    int N, int K, int m0, int n0)
{
    extern __shared__ __nv_bfloat16 sm_bf[];
    const unsigned sbase = (unsigned)__cvta_generic_to_shared(sm_bf);

    const int tid  = threadIdx.x;
    const int lane = tid & 31, warp = tid >> 5;
    const int wm = (warp >> 2) << 6;
    const int wn = (warp & 3)  << 5;
    const int g = lane >> 2, t = lane & 3;
    const int KT = K >> 5;

    const __nv_bfloat16* Agh = Ah + (size_t)m0 * K;
    const __nv_bfloat16* Agl = Al + (size_t)m0 * K;
    const __nv_bfloat16* Bgh = Bh + (size_t)n0 * K;
    const __nv_bfloat16* Bgl = Bl + (size_t)n0 * K;

    const int sr = tid >> 2;
    const int scol = (tid & 3) << 3;

    float acc[4][4][4];
    #pragma unroll
    for (int i = 0; i < 4; i++)
        #pragma unroll
        for (int j = 0; j < 4; j++)
            #pragma unroll
            for (int q = 0; q < 4; q++) acc[i][j][q] = 0.f;

    const int arow = lane & 15;
    const int acol = (lane >> 4) << 3;
    const int brow = (lane & 7) | ((lane >> 1) & 8);
    const int bcol = lane & 8;

    {
        #pragma unroll
        for (int i = 0; i < 2; i++) {
            const int r = (i << 6) + sr;
            const unsigned d0 = sbase + (unsigned)(((0*2 + 0)*128 + r)*ASTR + scol) * 2;
            const unsigned d1 = sbase + (unsigned)(((0*2 + 1)*128 + r)*ASTR + scol) * 2;
            const unsigned d2 = sbase + (unsigned)((BOFF + ((0*2 + 0)*128 + r)*ASTR + scol)) * 2;
            const unsigned d3 = sbase + (unsigned)((BOFF + ((0*2 + 1)*128 + r)*ASTR + scol)) * 2;
            cpasync16(d0, Agh + (size_t)r * K + scol);
            cpasync16(d1, Agl + (size_t)r * K + scol);
            cpasync16(d2, Bgh + (size_t)r * K + scol);
            cpasync16(d3, Bgl + (size_t)r * K + scol);
        }
        cpcommit();
    }

    for (int kt = 0; kt < KT; kt++) {
        const int buf = kt & 1;
        if (kt + 1 < KT) {
            const int ko = (kt + 1) << 5;
            const int nb = buf ^ 1;
            #pragma unroll
            for (int i = 0; i < 2; i++) {
                const int r = (i << 6) + sr;
                const unsigned d0 = sbase + (unsigned)(((nb*2 + 0)*128 + r)*ASTR + scol) * 2;
                const unsigned d1 = sbase + (unsigned)(((nb*2 + 1)*128 + r)*ASTR + scol) * 2;
                const unsigned d2 = sbase + (unsigned)((BOFF + ((nb*2 + 0)*128 + r)*ASTR + scol)) * 2;
                const unsigned d3 = sbase + (unsigned)((BOFF + ((nb*2 + 1)*128 + r)*ASTR + scol)) * 2;
                cpasync16(d0, Agh + (size_t)r * K + ko + scol);
                cpasync16(d1, Agl + (size_t)r * K + ko + scol);
                cpasync16(d2, Bgh + (size_t)r * K + ko + scol);
                cpasync16(d3, Bgl + (size_t)r * K + ko + scol);
            }
            cpcommit();
            cpwait<1>();
        } else {
            cpwait<0>();
        }
        __syncthreads();

        const unsigned aHi = sbase + (unsigned)((buf*2 + 0)*128*ASTR) * 2;
        const unsigned aLo = sbase + (unsigned)((buf*2 + 1)*128*ASTR) * 2;
        const unsigned bHi = sbase + (unsigned)((BOFF + (buf*2 + 0)*128*ASTR)) * 2;
        const unsigned bLo = sbase + (unsigned)((BOFF + (buf*2 + 1)*128*ASTR)) * 2;

        #pragma unroll
        for (int ks = 0; ks < 2; ks++) {
            const int kc = ks << 4;
            unsigned bh[2][4], bl[2][4];
            #pragma unroll
            for (int np = 0; np < 2; np++) {
                const unsigned bo = (unsigned)((wn + (np << 4) + brow)*ASTR + kc + bcol) * 2;
                ldsm4(bh[np], bHi + bo);
                ldsm4(bl[np], bLo + bo);
            }
            #pragma unroll
            for (int mh = 0; mh < 2; mh++) {
                unsigned ah[2][4], al[2][4];
                #pragma unroll
                for (int m2 = 0; m2 < 2; m2++) {
                    const unsigned ao = (unsigned)((wm + ((mh*2 + m2) << 4) + arow)*ASTR + kc + acol) * 2;
                    ldsm4(ah[m2], aHi + ao);
                    ldsm4(al[m2], aLo + ao);
                }
                #pragma unroll
                for (int m2 = 0; m2 < 2; m2++) {
                    #pragma unroll
                    for (int nt = 0; nt < 4; nt++)
                        mma16816(acc[mh*2 + m2][nt], ah[m2], bh[nt >> 1] + ((nt & 1) << 1));
                    #pragma unroll
                    for (int nt = 0; nt < 4; nt++)
                        mma16816(acc[mh*2 + m2][nt], ah[m2], bl[nt >> 1] + ((nt & 1) << 1));
                    #pragma unroll
                    for (int nt = 0; nt < 4; nt++)
                        mma16816(acc[mh*2 + m2][nt], al[m2], bh[nt >> 1] + ((nt & 1) << 1));
                }
            }
        }
        __syncthreads();
    }

    #pragma unroll
    for (int mt = 0; mt < 4; mt++) {
        const int row = m0 + wm + (mt << 4) + g;
        #pragma unroll
        for (int nt = 0; nt < 4; nt++) {
            const int col = n0 + wn + (nt << 3) + (t << 1);
            float bx = 0.f, by = 0.f;
            if (bias) { bx = bias[col]; by = bias[col + 1]; }
            float v0 = acc[mt][nt][0] + bx, v1 = acc[mt][nt][1] + by;
            float v2 = acc[mt][nt][2] + bx, v3 = acc[mt][nt][3] + by;
            if (MODE & 1) {
                v0 = fmaxf(v0, 0.f); v1 = fmaxf(v1, 0.f);
                v2 = fmaxf(v2, 0.f); v3 = fmaxf(v3, 0.f);
            }
            if (MODE & 2) {
                unsigned h01, l01, h23, l23;
                packsplit(v0, v1, h01, l01);
                packsplit(v2, v3, h23, l23);
                *(unsigned*)(Chi + (size_t)row * N + col)       = h01;
                *(unsigned*)(Clo + (size_t)row * N + col)       = l01;
                *(unsigned*)(Chi + (size_t)(row + 8) * N + col) = h23;
                *(unsigned*)(Clo + (size_t)(row + 8) * N + col) = l23;
            } else {
                *(float2*)(C + (size_t)row * N + col)       = make_float2(v0, v1);
                *(float2*)(C + (size_t)(row + 8) * N + col) = make_float2(v2, v3);
            }
        }
    }
}

template<int MODE>
__global__ __launch_bounds__(256, 2) void gemm_kernel(
    const __nv_bfloat16* __restrict__ Ah, const __nv_bfloat16* __restrict__ Al,
    const __nv_bfloat16* __restrict__ Bh, const __nv_bfloat16* __restrict__ Bl,
    const float* __restrict__ bias, float* __restrict__ C,
    __nv_bfloat16* __restrict__ Chi, __nv_bfloat16* __restrict__ Clo, int N, int K)
{
    gemm_core<MODE>(Ah, Al, Bh, Bl, bias, C, Chi, Clo, N, K,
                    blockIdx.y << 7, blockIdx.x << 7);
}

__global__ __launch_bounds__(256, 2) void gemm_qkv_kernel(
    const __nv_bfloat16* __restrict__ xh, const __nv_bfloat16* __restrict__ xl,
    const __nv_bfloat16* __restrict__ wh, const __nv_bfloat16* __restrict__ wl,
    __nv_bfloat16* __restrict__ qh, __nv_bfloat16* __restrict__ ql,
    __nv_bfloat16* __restrict__ kh, __nv_bfloat16* __restrict__ kl,
    __nv_bfloat16* __restrict__ vh, __nv_bfloat16* __restrict__ vl)
{
    const int z = blockIdx.z;
    const int mat = z >> 2, h = z & 3;
    const size_t woff = (size_t)mat * 262144 + (size_t)h * 65536;
    __nv_bfloat16* Chi = (mat == 0 ? qh : mat == 1 ? kh : vh) + (size_t)h * MTOK * HD;
    __nv_bfloat16* Clo = (mat == 0 ? ql : mat == 1 ? kl : vl) + (size_t)h * MTOK * HD;
    gemm_core<2>(xh, xl, wh + woff, wl + woff, nullptr, nullptr, Chi, Clo, HD, HD,
                 blockIdx.y << 7, blockIdx.x << 7);
}

// =================================================================
// flash v5.1: 128 q-rows/CTA, 32-key tiles, 8 warps (16 rows each),
// cp.async fills, rescale skip + interleaved mma.
// =================================================================
#define QS 264
#define FLASH_SMEM ((2*128 + 4*32)*QS*2)   // 202752 B
#define L2E 1.4426950408889634f

__global__ __launch_bounds__(256, 1) void flash_mma_kernel(
    const __nv_bfloat16* __restrict__ qh, const __nv_bfloat16* __restrict__ ql,
    const __nv_bfloat16* __restrict__ kh, const __nv_bfloat16* __restrict__ kl,
    const __nv_bfloat16* __restrict__ vh, const __nv_bfloat16* __restrict__ vl,
    const int* __restrict__ amask,
    __nv_bfloat16* __restrict__ atth, __nv_bfloat16* __restrict__ attl)
{
    extern __shared__ __nv_bfloat16 sm[];
    __nv_bfloat16* sQh = sm;
    __nv_bfloat16* sQl = sQh + 128*QS;
    __nv_bfloat16* sKh = sQl + 128*QS;
    __nv_bfloat16* sKl = sKh + 32*QS;
    __nv_bfloat16* sVh = sKl + 32*QS;
    __nv_bfloat16* sVl = sVh + 32*QS;
    __shared__ int sMq[128];
    __shared__ int sMk[32];

    const int tid  = threadIdx.x;
    const int lane = tid & 31, w = tid >> 5;
    const int g = lane >> 2, t = lane & 3;
    const int bh = blockIdx.y;
    const int b = bh >> 2, h = bh & 3;
    const int qidx = (int)gridDim.x - 1 - (int)blockIdx.x;   // heavy first
    const int m0 = qidx << 7;
    const size_t base = ((size_t)h * MTOK + (size_t)b * SEQ) * HD;

    const unsigned bQh = (unsigned)__cvta_generic_to_shared(sQh);
    const unsigned bQl = (unsigned)__cvta_generic_to_shared(sQl);
    const unsigned bKh = (unsigned)__cvta_generic_to_shared(sKh);
    const unsigned bKl = (unsigned)__cvta_generic_to_shared(sKl);
    const unsigned bVh = (unsigned)__cvta_generic_to_shared(sVh);
    const unsigned bVl = (unsigned)__cvta_generic_to_shared(sVl);

    const unsigned offA = (((w << 4) + (lane & 15)) * QS + ((lane >> 4) << 3)) * 2;
    const unsigned offB = ((((lane & 7) | ((lane >> 1) & 8)) * QS) + (lane & 8)) * 2;
    const unsigned offV = (((lane & 15) * QS) + ((lane >> 4) << 3)) * 2;

    // ---- Q fill via cp.async ----
    {
        const __nv_bfloat16* Qh = qh + base + (size_t)m0 * HD;
        const __nv_bfloat16* Ql = ql + base + (size_t)m0 * HD;
        for (int i = tid; i < 4096; i += 256) {
            int r = i >> 5, c = (i & 31) << 3;
            cpasync16(bQh + (unsigned)(r*QS + c)*2, Qh + (size_t)r*HD + c);
            cpasync16(bQl + (unsigned)(r*QS + c)*2, Ql + (size_t)r*HD + c);
        }
        if (tid < 128) sMq[tid] = amask[b * SEQ + m0 + tid];
    }

    float accO[32][4];
    #pragma unroll
    for (int i = 0; i < 32; i++)
        #pragma unroll
        for (int j = 0; j < 4; j++) accO[i][j] = 0.f;
    float m_run0 = -1e30f, m_run1 = -1e30f, l_run0 = 0.f, l_run1 = 0.f;

    const int gi0 = m0 + (w << 4) + g;
    const int gi1 = gi0 + 8;

    const int ntiles = (qidx + 1) << 2;
    for (int kt = 0; kt < ntiles; kt++) {
        const int j0 = kt << 5;
        __syncthreads();
        {
            const __nv_bfloat16* Kh = kh + base + (size_t)j0 * HD;
            const __nv_bfloat16* Kl = kl + base + (size_t)j0 * HD;
            const __nv_bfloat16* Vh = vh + base + (size_t)j0 * HD;
            const __nv_bfloat16* Vl = vl + base + (size_t)j0 * HD;
            for (int i = tid; i < 1024; i += 256) {
                int r = i >> 5, c = (i & 31) << 3;
                const unsigned so = (unsigned)(r*QS + c) * 2;
                const size_t go = (size_t)r*HD + c;
                cpasync16(bKh + so, Kh + go);
                cpasync16(bKl + so, Kl + go);
                cpasync16(bVh + so, Vh + go);
                cpasync16(bVl + so, Vl + go);
            }
            if (tid < 32) sMk[tid] = amask[b * SEQ + j0 + tid];
            cpcommit();
            cpwait<0>();
        }
        __syncthreads();

        // ---- scores: 16 rows x 32 keys per warp (interleaved) ----
        float sc[4][4];
        #pragma unroll
        for (int i = 0; i < 4; i++)
            #pragma unroll
            for (int j = 0; j < 4; j++) sc[i][j] = 0.f;

        #pragma unroll 4
        for (int ks = 0; ks < 16; ks++) {
            unsigned aqh[4], aql[4];
            ldsm4(aqh, bQh + offA + ks*32);
            ldsm4(aql, bQl + offA + ks*32);
            #pragma unroll
            for (int p = 0; p < 2; p++) {
                unsigned kbh[4], kbl[4];
                ldsm4(kbh, bKh + offB + p*(16*QS*2) + ks*32);
                ldsm4(kbl, bKl + offB + p*(16*QS*2) + ks*32);
                mma16816(sc[2*p],   aqh, kbh);
                mma16816(sc[2*p+1], aqh, kbh+2);
                mma16816(sc[2*p],   aqh, kbl);
                mma16816(sc[2*p+1], aqh, kbl+2);
                mma16816(sc[2*p],   aql, kbh);
                mma16816(sc[2*p+1], aql, kbh+2);
            }
        }

        // ---- mask + online softmax ----
        const int qm0 = sMq[(w << 4) + g];
        const int qm1 = sMq[(w << 4) + g + 8];
        float mx0 = -1e30f, mx1 = -1e30f;
        #pragma unroll
        for (int nt = 0; nt < 4; nt++) {
            const int jb = (nt << 3) + (t << 1);
            const int k0 = sMk[jb], k1 = sMk[jb + 1];
            const int gj0 = j0 + jb, gj1 = gj0 + 1;
            sc[nt][0] = (qm0 && k0 && gj0 <= gi0) ? sc[nt][0] * 0.0625f : -1e30f;
            sc[nt][1] = (qm0 && k1 && gj1 <= gi0) ? sc[nt][1] * 0.0625f : -1e30f;
            sc[nt][2] = (qm1 && k0 && gj0 <= gi1) ? sc[nt][2] * 0.0625f : -1e30f;
            sc[nt][3] = (qm1 && k1 && gj1 <= gi1) ? sc[nt][3] * 0.0625f : -1e30f;
            mx0 = fmaxf(mx0, fmaxf(sc[nt][0], sc[nt][1]));
            mx1 = fmaxf(mx1, fmaxf(sc[nt][2], sc[nt][3]));
        }
        mx0 = fmaxf(mx0, __shfl_xor_sync(0xffffffffu, mx0, 1, 4));
        mx0 = fmaxf(mx0, __shfl_xor_sync(0xffffffffu, mx0, 2, 4));
        mx1 = fmaxf(mx1, __shfl_xor_sync(0xffffffffu, mx1, 1, 4));
        mx1 = fmaxf(mx1, __shfl_xor_sync(0xffffffffu, mx1, 2, 4));

        const float mn0 = fmaxf(m_run0, mx0);
        const float mn1 = fmaxf(m_run1, mx1);
        const float al0 = exp2f((m_run0 - mn0) * L2E);
        const float al1 = exp2f((m_run1 - mn1) * L2E);
        m_run0 = mn0; m_run1 = mn1;

        float ps0 = 0.f, ps1 = 0.f;
        #pragma unroll
        for (int nt = 0; nt < 4; nt++) {
            float p0 = exp2f((sc[nt][0] - mn0) * L2E);
            float p1 = exp2f((sc[nt][1] - mn0) * L2E);
            float p2 = exp2f((sc[nt][2] - mn1) * L2E);
            float p3 = exp2f((sc[nt][3] - mn1) * L2E);
            sc[nt][0] = p0; sc[nt][1] = p1; sc[nt][2] = p2; sc[nt][3] = p3;
            ps0 += p0 + p1; ps1 += p2 + p3;
        }
        ps0 += __shfl_xor_sync(0xffffffffu, ps0, 1, 4);
        ps0 += __shfl_xor_sync(0xffffffffu, ps0, 2, 4);
        ps1 += __shfl_xor_sync(0xffffffffu, ps1, 1, 4);
        ps1 += __shfl_xor_sync(0xffffffffu, ps1, 2, 4);
        l_run0 = l_run0 * al0 + ps0;
        l_run1 = l_run1 * al1 + ps1;

        // warp-uniform skip of identity rescale
        const bool skip = __all_sync(0xffffffffu, (al0 == 1.f) && (al1 == 1.f));
        if (!skip) {
            #pragma unroll
            for (int i = 0; i < 32; i++) {
                accO[i][0] *= al0; accO[i][1] *= al0;
                accO[i][2] *= al1; accO[i][3] *= al1;
            }
        }

        // ---- O += P * V (interleaved) ----
        #pragma unroll
        for (int ks = 0; ks < 2; ks++) {
            unsigned aPh[4], aPl[4];
            packsplit(sc[2*ks][0],   sc[2*ks][1],   aPh[0], aPl[0]);
            packsplit(sc[2*ks][2],   sc[2*ks][3],   aPh[1], aPl[1]);
            packsplit(sc[2*ks+1][0], sc[2*ks+1][1], aPh[2], aPl[2]);
            packsplit(sc[2*ks+1][2], sc[2*ks+1][3], aPh[3], aPl[3]);
            #pragma unroll
            for (int nv = 0; nv < 16; nv++) {
                unsigned vbh[4], vbl[4];
                ldsm4t(vbh, bVh + offV + ks*(16*QS*2) + nv*32);
                ldsm4t(vbl, bVl + offV + ks*(16*QS*2) + nv*32);
                mma16816(accO[2*nv],   aPh, vbh);
                mma16816(accO[2*nv+1], aPh, vbh+2);
                mma16816(accO[2*nv],   aPh, vbl);
                mma16816(accO[2*nv+1], aPh, vbl+2);
                mma16816(accO[2*nv],   aPl, vbh);
                mma16816(accO[2*nv+1], aPl, vbh+2);
            }
        }
    }

    // ---- epilogue ----
    const int qm0 = sMq[(w << 4) + g];
    const int qm1 = sMq[(w << 4) + g + 8];
    const float inv0 = (qm0 && l_run0 > 0.f) ? (1.f / l_run0) : 0.f;
    const float inv1 = (qm1 && l_run1 > 0.f) ? (1.f / l_run1) : 0.f;
    const size_t o0 = (size_t)(b * SEQ + gi0) * (NH * HD) + h * HD;
    const size_t o1 = (size_t)(b * SEQ + gi1) * (NH * HD) + h * HD;
    #pragma unroll
    for (int nt = 0; nt < 32; nt++) {
        const int col = (nt << 3) + (t << 1);
        unsigned h0, l0, h1, l1;
        packsplit(accO[nt][0] * inv0, accO[nt][1] * inv0, h0, l0);
        packsplit(accO[nt][2] * inv1, accO[nt][3] * inv1, h1, l1);
        *(unsigned*)(atth + o0 + col) = h0;
        *(unsigned*)(attl + o0 + col) = l0;
        *(unsigned*)(atth + o1 + col) = h1;
        *(unsigned*)(attl + o1 + col) = l1;
    }
}

// ---------------- fused residual-add + LayerNorm ----------------
template<int SPLIT>
__global__ __launch_bounds__(256) void add_ln_kernel(
    const float* __restrict__ a, const float* __restrict__ b2,
    const float* __restrict__ g, const float* __restrict__ be,
    float* __restrict__ out,
    __nv_bfloat16* __restrict__ oh, __nv_bfloat16* __restrict__ ol)
{
    __shared__ float red[16];
    const int row = blockIdx.x, t = threadIdx.x;
    const size_t off = (size_t)row * HD + t;
    const float v = a[off] + b2[off];
    float sv = v, sq = v * v;
    #pragma unroll
    for (int o = 16; o; o >>= 1) {
        sv += __shfl_xor_sync(0xffffffffu, sv, o);
        sq += __shfl_xor_sync(0xffffffffu, sq, o);
    }
    if ((t & 31) == 0) { red[t >> 5] = sv; red[8 + (t >> 5)] = sq; }
    __syncthreads();
    if (t == 0) {
        float s1 = 0.f, s2 = 0.f;
        #pragma unroll
        for (int i = 0; i < 8; i++) { s1 += red[i]; s2 += red[8 + i]; }
        red[0] = s1; red[8] = s2;
    }
    __syncthreads();
    const float mu  = red[0] * (1.f / 256.f);
    const float var = red[8] * (1.f / 256.f) - mu * mu;
    const float r = (v - mu) * rsqrtf(var + 1e-5f) * g[t] + be[t];
    out[off] = r;
    if (SPLIT) {
        __nv_bfloat16 hi = __float2bfloat16_rn(r);
        oh[off] = hi;
        ol[off] = __float2bfloat16_rn(r - __bfloat162float(hi));
    }
}

// ---------------- launch ----------------
extern "C" void kernel_launch(void* const* d_in, const int* in_sizes, int n_in,
                              void* d_out, int out_size)
{
    const float* x    = (const float*)d_in[0];
    const int*   am   = (const int*  )d_in[1];
    const float* wq   = (const float*)d_in[2];
    const float* wk   = (const float*)d_in[3];
    const float* wv   = (const float*)d_in[4];
    const float* wo_w = (const float*)d_in[5];
    const float* wo_b = (const float*)d_in[6];
    const float* ln1g = (const float*)d_in[7];
    const float* ln1b = (const float*)d_in[8];
    const float* f1w  = (const float*)d_in[9];
    const float* f1b  = (const float*)d_in[10];
    const float* f2w  = (const float*)d_in[11];
    const float* f2b  = (const float*)d_in[12];
    const float* ln2g = (const float*)d_in[13];
    const float* ln2b = (const float*)d_in[14];
    float* out = (float*)d_out;
    (void)in_sizes; (void)n_in; (void)out_size;

    __nv_bfloat16 *pxh, *pxl, *pwh, *pwl, *pqh, *pql, *pkh, *pkl, *pvh, *pvl;
    __nv_bfloat16 *path, *patl, *px1h, *px1l, *phh, *phl;
    float *px1, *pt1;
    cudaGetSymbolAddress((void**)&pxh, g_xh);
    cudaGetSymbolAddress((void**)&pxl, g_xl);
    cudaGetSymbolAddress((void**)&pwh, g_wh);
    cudaGetSymbolAddress((void**)&pwl, g_wl);
    cudaGetSymbolAddress((void**)&pqh, g_qh);
    cudaGetSymbolAddress((void**)&pql, g_ql);
    cudaGetSymbolAddress((void**)&pkh, g_kh);
    cudaGetSymbolAddress((void**)&pkl, g_kl);
    cudaGetSymbolAddress((void**)&pvh, g_vh);
    cudaGetSymbolAddress((void**)&pvl, g_vl);
    cudaGetSymbolAddress((void**)&path, g_ath);
    cudaGetSymbolAddress((void**)&patl, g_atl);
    cudaGetSymbolAddress((void**)&px1h, g_x1h);
    cudaGetSymbolAddress((void**)&px1l, g_x1l);
    cudaGetSymbolAddress((void**)&phh, g_hh);
    cudaGetSymbolAddress((void**)&phl, g_hl);
    cudaGetSymbolAddress((void**)&px1, g_x1);
    cudaGetSymbolAddress((void**)&pt1, g_t1);

    cudaFuncSetAttribute(gemm_qkv_kernel, cudaFuncAttributeMaxDynamicSharedMemorySize, GEMM_SMEM);
    cudaFuncSetAttribute(gemm_kernel<0>,  cudaFuncAttributeMaxDynamicSharedMemorySize, GEMM_SMEM);
    cudaFuncSetAttribute(gemm_kernel<3>,  cudaFuncAttributeMaxDynamicSharedMemorySize, GEMM_SMEM);
    cudaFuncSetAttribute(flash_mma_kernel, cudaFuncAttributeMaxDynamicSharedMemorySize, FLASH_SMEM);

    // ---- pre-split x and weights ----
    split_x_kernel<<<MTOK*HD/1024, 256>>>(x, pxh, pxl);
    split_w_kernel<<<WTOT/1024, 256>>>(wq, wk, wv, wo_w, f1w, f2w, pwh, pwl);

    // ---- QKV projections ----
    gemm_qkv_kernel<<<dim3(HD/128, MTOK/128, 12), 256, GEMM_SMEM>>>(
        pxh, pxl, pwh, pwl, pqh, pql, pkh, pkl, pvh, pvl);

    // ---- causal flash attention (v5.1) ----
    flash_mma_kernel<<<dim3(SEQ/128, BATCH*NH), 256, FLASH_SMEM>>>(
        pqh, pql, pkh, pkl, pvh, pvl, am, path, patl);

    // ---- output projection + residual/LN1 ----
    gemm_kernel<0><<<dim3(HD/128, MTOK/128), 256, GEMM_SMEM>>>(
        path, patl, pwh + WOFF_O, pwl + WOFF_O, wo_b, pt1, nullptr, nullptr, HD, NH*HD);
    add_ln_kernel<1><<<MTOK, 256>>>(x, pt1, ln1g, ln1b, px1, px1h, px1l);

    // ---- FFN ----
    gemm_kernel<3><<<dim3(FF/128, MTOK/128), 256, GEMM_SMEM>>>(
        px1h, px1l, pwh + WOFF_F1, pwl + WOFF_F1, f1b, nullptr, phh, phl, FF, HD);
    gemm_kernel<0><<<dim3(HD/128, MTOK/128), 256, GEMM_SMEM>>>(
        phh, phl, pwh + WOFF_F2, pwl + WOFF_F2, f2b, pt1, nullptr, nullptr, HD, FF);
    add_ln_kernel<0><<<MTOK, 256>>>(px1, pt1, ln2g, ln2b, out, nullptr, nullptr);
}

// round 14
// speedup vs baseline: 1.2590x; 1.1713x over previous
#include <cuda_runtime.h>
#include <cuda_fp16.h>
#include <math.h>
#include <stdint.h>

// ---------------- problem constants ----------------
#define NH    4
#define HD    256
#define SEQ   1024
#define BATCH 8
#define MTOK  (BATCH*SEQ)
#define FF    1024

#define WOFF_Q  0
#define WOFF_K  262144
#define WOFF_V  524288
#define WOFF_O  786432
#define WOFF_F1 1048576
#define WOFF_F2 1310720
#define WTOT    1572864

// ---------------- scratch (fp16 split world) ----------------
__device__ __align__(16) __half g_xh [(size_t)MTOK*HD];
__device__ __align__(16) __half g_xl [(size_t)MTOK*HD];
__device__ __align__(16) __half g_wh [(size_t)WTOT];
__device__ __align__(16) __half g_wl [(size_t)WTOT];
__device__ __align__(16) __half g_qh [(size_t)NH*MTOK*HD];
__device__ __align__(16) __half g_ql [(size_t)NH*MTOK*HD];
__device__ __align__(16) __half g_kh [(size_t)NH*MTOK*HD];
__device__ __align__(16) __half g_kl [(size_t)NH*MTOK*HD];
__device__ __align__(16) __half g_vh [(size_t)NH*MTOK*HD];
__device__ __align__(16) __half g_vl [(size_t)NH*MTOK*HD];
__device__ __align__(16) __half g_ath[(size_t)MTOK*NH*HD];
__device__ __align__(16) __half g_atl[(size_t)MTOK*NH*HD];
__device__ __align__(16) __half g_x1h[(size_t)MTOK*HD];
__device__ __align__(16) __half g_x1l[(size_t)MTOK*HD];
__device__ __align__(16) __half g_hh [(size_t)MTOK*FF];
__device__ __align__(16) __half g_hl [(size_t)MTOK*FF];
__device__ float g_x1 [(size_t)MTOK*HD];
__device__ float g_t1 [(size_t)MTOK*HD];

// ---------------- helpers ----------------
__device__ __forceinline__ void packsplit(float a, float b, unsigned& hi, unsigned& lo)
{
    __half ah = __float2half_rn(a);
    __half bh = __float2half_rn(b);
    __half2 h = __halves2half2(ah, bh);
    __half2 l = __floats2half2_rn(a - __half2float(ah), b - __half2float(bh));
    hi = *reinterpret_cast<unsigned*>(&h);
    lo = *reinterpret_cast<unsigned*>(&l);
}

__device__ __forceinline__ void split8(__half* hi_p, __half* lo_p, float4 v)
{
    unsigned h01, l01, h23, l23;
    packsplit(v.x, v.y, h01, l01);
    packsplit(v.z, v.w, h23, l23);
    *reinterpret_cast<uint2*>(hi_p) = make_uint2(h01, h23);
    *reinterpret_cast<uint2*>(lo_p) = make_uint2(l01, l23);
}

__device__ __forceinline__ void mma16816(float* c, const unsigned* a, const unsigned* b)
{
    asm volatile(
        "mma.sync.aligned.m16n8k16.row.col.f32.f16.f16.f32 "
        "{%0,%1,%2,%3}, {%4,%5,%6,%7}, {%8,%9}, {%0,%1,%2,%3};\n"
        : "+f"(c[0]), "+f"(c[1]), "+f"(c[2]), "+f"(c[3])
        : "r"(a[0]), "r"(a[1]), "r"(a[2]), "r"(a[3]), "r"(b[0]), "r"(b[1]));
}

__device__ __forceinline__ void ldsm4(unsigned* d, unsigned addr)
{
    asm volatile("ldmatrix.sync.aligned.m8n8.x4.shared.b16 {%0,%1,%2,%3}, [%4];"
                 : "=r"(d[0]), "=r"(d[1]), "=r"(d[2]), "=r"(d[3]) : "r"(addr));
}

__device__ __forceinline__ void ldsm4t(unsigned* d, unsigned addr)
{
    asm volatile("ldmatrix.sync.aligned.m8n8.x4.trans.shared.b16 {%0,%1,%2,%3}, [%4];"
                 : "=r"(d[0]), "=r"(d[1]), "=r"(d[2]), "=r"(d[3]) : "r"(addr));
}

__device__ __forceinline__ void cpasync16(unsigned dst, const void* src)
{
    asm volatile("cp.async.cg.shared.global [%0], [%1], 16;" :: "r"(dst), "l"(src));
}
__device__ __forceinline__ void cpcommit()
{
    asm volatile("cp.async.commit_group;" ::: "memory");
}
template<int N>
__device__ __forceinline__ void cpwait()
{
    asm volatile("cp.async.wait_group %0;" :: "n"(N) : "memory");
}

// ---------------- pre-split kernels ----------------
__global__ __launch_bounds__(256) void split_x_kernel(
    const float* __restrict__ x, __half* __restrict__ oh, __half* __restrict__ ol)
{
    const size_t e = ((size_t)blockIdx.x * 256 + threadIdx.x) * 4;
    if (e >= (size_t)MTOK * HD) return;
    split8(oh + e, ol + e, *(const float4*)(x + e));
}

__global__ __launch_bounds__(256) void split_w_kernel(
    const float* __restrict__ wq, const float* __restrict__ wk, const float* __restrict__ wv,
    const float* __restrict__ wo, const float* __restrict__ f1, const float* __restrict__ f2,
    __half* __restrict__ oh, __half* __restrict__ ol)
{
    const size_t e = ((size_t)blockIdx.x * 256 + threadIdx.x) * 4;
    if (e >= (size_t)WTOT) return;
    const float* src; size_t off;
    if      (e < WOFF_K)  { src = wq; off = WOFF_Q;  }
    else if (e < WOFF_V)  { src = wk; off = WOFF_K;  }
    else if (e < WOFF_O)  { src = wv; off = WOFF_V;  }
    else if (e < WOFF_F1) { src = wo; off = WOFF_O;  }
    else if (e < WOFF_F2) { src = f1; off = WOFF_F1; }
    else                  { src = f2; off = WOFF_F2; }
    split8(oh + e, ol + e, *(const float4*)(src + (e - off)));
}

// =================================================================
// fp16x3 GEMM: cp.async + ldmatrix, 2 CTAs/SM, interleaved mma.
// =================================================================
#define ASTR 40
#define BOFF (2*2*128*ASTR)
#define GEMM_SMEM (2*2*128*ASTR*2*2)

template<int MODE>
__device__ __forceinline__ void gemm_core(
    const __half* __restrict__ Ah, const __half* __restrict__ Al,
    const __half* __restrict__ Bh, const __half* __restrict__ Bl,
    const float* __restrict__ bias, float* __restrict__ C,
    __half* __restrict__ Chi, __half* __restrict__ Clo,
    int N, int K, int m0, int n0)
{
    extern __shared__ __half sm_bf[];
    const unsigned sbase = (unsigned)__cvta_generic_to_shared(sm_bf);

    const int tid  = threadIdx.x;
    const int lane = tid & 31, warp = tid >> 5;
    const int wm = (warp >> 2) << 6;
    const int wn = (warp & 3)  << 5;
    const int g = lane >> 2, t = lane & 3;
    const int KT = K >> 5;

    const __half* Agh = Ah + (size_t)m0 * K;
    const __half* Agl = Al + (size_t)m0 * K;
    const __half* Bgh = Bh + (size_t)n0 * K;
    const __half* Bgl = Bl + (size_t)n0 * K;

    const int sr = tid >> 2;
    const int scol = (tid & 3) << 3;

    float acc[4][4][4];
    #pragma unroll
    for (int i = 0; i < 4; i++)
        #pragma unroll
        for (int j = 0; j < 4; j++)
            #pragma unroll
            for (int q = 0; q < 4; q++) acc[i][j][q] = 0.f;

    const int arow = lane & 15;
    const int acol = (lane >> 4) << 3;
    const int brow = (lane & 7) | ((lane >> 1) & 8);
    const int bcol = lane & 8;

    {
        #pragma unroll
        for (int i = 0; i < 2; i++) {
            const int r = (i << 6) + sr;
            const unsigned d0 = sbase + (unsigned)(((0*2 + 0)*128 + r)*ASTR + scol) * 2;
            const unsigned d1 = sbase + (unsigned)(((0*2 + 1)*128 + r)*ASTR + scol) * 2;
            const unsigned d2 = sbase + (unsigned)((BOFF + ((0*2 + 0)*128 + r)*ASTR + scol)) * 2;
            const unsigned d3 = sbase + (unsigned)((BOFF + ((0*2 + 1)*128 + r)*ASTR + scol)) * 2;
            cpasync16(d0, Agh + (size_t)r * K + scol);
            cpasync16(d1, Agl + (size_t)r * K + scol);
            cpasync16(d2, Bgh + (size_t)r * K + scol);
            cpasync16(d3, Bgl + (size_t)r * K + scol);
        }
        cpcommit();
    }

    for (int kt = 0; kt < KT; kt++) {
        const int buf = kt & 1;
        if (kt + 1 < KT) {
            const int ko = (kt + 1) << 5;
            const int nb = buf ^ 1;
            #pragma unroll
            for (int i = 0; i < 2; i++) {
                const int r = (i << 6) + sr;
                const unsigned d0 = sbase + (unsigned)(((nb*2 + 0)*128 + r)*ASTR + scol) * 2;
                const unsigned d1 = sbase + (unsigned)(((nb*2 + 1)*128 + r)*ASTR + scol) * 2;
                const unsigned d2 = sbase + (unsigned)((BOFF + ((nb*2 + 0)*128 + r)*ASTR + scol)) * 2;
                const unsigned d3 = sbase + (unsigned)((BOFF + ((nb*2 + 1)*128 + r)*ASTR + scol)) * 2;
                cpasync16(d0, Agh + (size_t)r * K + ko + scol);
                cpasync16(d1, Agl + (size_t)r * K + ko + scol);
                cpasync16(d2, Bgh + (size_t)r * K + ko + scol);
                cpasync16(d3, Bgl + (size_t)r * K + ko + scol);
            }
            cpcommit();
            cpwait<1>();
        } else {
            cpwait<0>();
        }
        __syncthreads();

        const unsigned aHi = sbase + (unsigned)((buf*2 + 0)*128*ASTR) * 2;
        const unsigned aLo = sbase + (unsigned)((buf*2 + 1)*128*ASTR) * 2;
        const unsigned bHi = sbase + (unsigned)((BOFF + (buf*2 + 0)*128*ASTR)) * 2;
        const unsigned bLo = sbase + (unsigned)((BOFF + (buf*2 + 1)*128*ASTR)) * 2;

        #pragma unroll
        for (int ks = 0; ks < 2; ks++) {
            const int kc = ks << 4;
            unsigned bh[2][4], bl[2][4];
            #pragma unroll
            for (int np = 0; np < 2; np++) {
                const unsigned bo = (unsigned)((wn + (np << 4) + brow)*ASTR + kc + bcol) * 2;
                ldsm4(bh[np], bHi + bo);
                ldsm4(bl[np], bLo + bo);
            }
            #pragma unroll
            for (int mh = 0; mh < 2; mh++) {
                unsigned ah[2][4], al[2][4];
                #pragma unroll
                for (int m2 = 0; m2 < 2; m2++) {
                    const unsigned ao = (unsigned)((wm + ((mh*2 + m2) << 4) + arow)*ASTR + kc + acol) * 2;
                    ldsm4(ah[m2], aHi + ao);
                    ldsm4(al[m2], aLo + ao);
                }
                #pragma unroll
                for (int m2 = 0; m2 < 2; m2++) {
                    #pragma unroll
                    for (int nt = 0; nt < 4; nt++)
                        mma16816(acc[mh*2 + m2][nt], ah[m2], bh[nt >> 1] + ((nt & 1) << 1));
                    #pragma unroll
                    for (int nt = 0; nt < 4; nt++)
                        mma16816(acc[mh*2 + m2][nt], ah[m2], bl[nt >> 1] + ((nt & 1) << 1));
                    #pragma unroll
                    for (int nt = 0; nt < 4; nt++)
                        mma16816(acc[mh*2 + m2][nt], al[m2], bh[nt >> 1] + ((nt & 1) << 1));
                }
            }
        }
        __syncthreads();
    }

    #pragma unroll
    for (int mt = 0; mt < 4; mt++) {
        const int row = m0 + wm + (mt << 4) + g;
        #pragma unroll
        for (int nt = 0; nt < 4; nt++) {
            const int col = n0 + wn + (nt << 3) + (t << 1);
            float bx = 0.f, by = 0.f;
            if (bias) { bx = bias[col]; by = bias[col + 1]; }
            float v0 = acc[mt][nt][0] + bx, v1 = acc[mt][nt][1] + by;
            float v2 = acc[mt][nt][2] + bx, v3 = acc[mt][nt][3] + by;
            if (MODE & 1) {
                v0 = fmaxf(v0, 0.f); v1 = fmaxf(v1, 0.f);
                v2 = fmaxf(v2, 0.f); v3 = fmaxf(v3, 0.f);
            }
            if (MODE & 2) {
                unsigned h01, l01, h23, l23;
                packsplit(v0, v1, h01, l01);
                packsplit(v2, v3, h23, l23);
                *(unsigned*)(Chi + (size_t)row * N + col)       = h01;
                *(unsigned*)(Clo + (size_t)row * N + col)       = l01;
                *(unsigned*)(Chi + (size_t)(row + 8) * N + col) = h23;
                *(unsigned*)(Clo + (size_t)(row + 8) * N + col) = l23;
            } else {
                *(float2*)(C + (size_t)row * N + col)       = make_float2(v0, v1);
                *(float2*)(C + (size_t)(row + 8) * N + col) = make_float2(v2, v3);
            }
        }
    }
}

template<int MODE>
__global__ __launch_bounds__(256, 2) void gemm_kernel(
    const __half* __restrict__ Ah, const __half* __restrict__ Al,
    const __half* __restrict__ Bh, const __half* __restrict__ Bl,
    const float* __restrict__ bias, float* __restrict__ C,
    __half* __restrict__ Chi, __half* __restrict__ Clo, int N, int K)
{
    gemm_core<MODE>(Ah, Al, Bh, Bl, bias, C, Chi, Clo, N, K,
                    blockIdx.y << 7, blockIdx.x << 7);
}

__global__ __launch_bounds__(256, 2) void gemm_qkv_kernel(
    const __half* __restrict__ xh, const __half* __restrict__ xl,
    const __half* __restrict__ wh, const __half* __restrict__ wl,
    __half* __restrict__ qh, __half* __restrict__ ql,
    __half* __restrict__ kh, __half* __restrict__ kl,
    __half* __restrict__ vh, __half* __restrict__ vl)
{
    const int z = blockIdx.z;
    const int mat = z >> 2, h = z & 3;
    const size_t woff = (size_t)mat * 262144 + (size_t)h * 65536;
    __half* Chi = (mat == 0 ? qh : mat == 1 ? kh : vh) + (size_t)h * MTOK * HD;
    __half* Clo = (mat == 0 ? ql : mat == 1 ? kl : vl) + (size_t)h * MTOK * HD;
    gemm_core<2>(xh, xl, wh + woff, wl + woff, nullptr, nullptr, Chi, Clo, HD, HD,
                 blockIdx.y << 7, blockIdx.x << 7);
}

// =================================================================
// flash v7: fp16; Q kept as hi/lo split; K,V hi-only (2-product).
// 128 q-rows/CTA, 32-key tiles, 8 warps.
// =================================================================
#define QS 264
#define FLASH_SMEM ((2*128 + 2*32)*QS*2)   // 168960 B
#define L2E 1.4426950408889634f

__global__ __launch_bounds__(256, 1) void flash_mma_kernel(
    const __half* __restrict__ qh, const __half* __restrict__ ql,
    const __half* __restrict__ kh, const __half* __restrict__ vh,
    const int* __restrict__ amask,
    __half* __restrict__ atth, __half* __restrict__ attl)
{
    extern __shared__ __half sm[];
    __half* sQh = sm;
    __half* sQl = sQh + 128*QS;
    __half* sKh = sQl + 128*QS;
    __half* sVh = sKh + 32*QS;
    __shared__ int sMq[128];
    __shared__ int sMk[32];

    const int tid  = threadIdx.x;
    const int lane = tid & 31, w = tid >> 5;
    const int g = lane >> 2, t = lane & 3;
    const int bh = blockIdx.y;
    const int b = bh >> 2, h = bh & 3;
    const int qidx = (int)gridDim.x - 1 - (int)blockIdx.x;   // heavy first
    const int m0 = qidx << 7;
    const size_t base = ((size_t)h * MTOK + (size_t)b * SEQ) * HD;

    const unsigned bQh = (unsigned)__cvta_generic_to_shared(sQh);
    const unsigned bQl = (unsigned)__cvta_generic_to_shared(sQl);
    const unsigned bKh = (unsigned)__cvta_generic_to_shared(sKh);
    const unsigned bVh = (unsigned)__cvta_generic_to_shared(sVh);

    const unsigned offA = (((w << 4) + (lane & 15)) * QS + ((lane >> 4) << 3)) * 2;
    const unsigned offB = ((((lane & 7) | ((lane >> 1) & 8)) * QS) + (lane & 8)) * 2;
    const unsigned offV = (((lane & 15) * QS) + ((lane >> 4) << 3)) * 2;

    // ---- Q fill via cp.async ----
    {
        const __half* Qh = qh + base + (size_t)m0 * HD;
        const __half* Ql = ql + base + (size_t)m0 * HD;
        for (int i = tid; i < 4096; i += 256) {
            int r = i >> 5, c = (i & 31) << 3;
            cpasync16(bQh + (unsigned)(r*QS + c)*2, Qh + (size_t)r*HD + c);
            cpasync16(bQl + (unsigned)(r*QS + c)*2, Ql + (size_t)r*HD + c);
        }
        if (tid < 128) sMq[tid] = amask[b * SEQ + m0 + tid];
    }

    float accO[32][4];
    #pragma unroll
    for (int i = 0; i < 32; i++)
        #pragma unroll
        for (int j = 0; j < 4; j++) accO[i][j] = 0.f;
    float m_run0 = -1e30f, m_run1 = -1e30f, l_run0 = 0.f, l_run1 = 0.f;

    const int gi0 = m0 + (w << 4) + g;
    const int gi1 = gi0 + 8;

    const int ntiles = (qidx + 1) << 2;
    for (int kt = 0; kt < ntiles; kt++) {
        const int j0 = kt << 5;
        __syncthreads();
        {
            const __half* Kh = kh + base + (size_t)j0 * HD;
            const __half* Vh = vh + base + (size_t)j0 * HD;
            for (int i = tid; i < 1024; i += 256) {
                int r = i >> 5, c = (i & 31) << 3;
                const unsigned so = (unsigned)(r*QS + c) * 2;
                const size_t go = (size_t)r*HD + c;
                cpasync16(bKh + so, Kh + go);
                cpasync16(bVh + so, Vh + go);
            }
            if (tid < 32) sMk[tid] = amask[b * SEQ + j0 + tid];
            cpcommit();
            cpwait<0>();
        }
        __syncthreads();

        // ---- scores: (Qh+Ql)·Kh, 16 rows x 32 keys per warp ----
        float sc[4][4];
        #pragma unroll
        for (int i = 0; i < 4; i++)
            #pragma unroll
            for (int j = 0; j < 4; j++) sc[i][j] = 0.f;

        #pragma unroll 4
        for (int ks = 0; ks < 16; ks++) {
            unsigned aqh[4], aql[4];
            ldsm4(aqh, bQh + offA + ks*32);
            ldsm4(aql, bQl + offA + ks*32);
            #pragma unroll
            for (int p = 0; p < 2; p++) {
                unsigned kbh[4];
                ldsm4(kbh, bKh + offB + p*(16*QS*2) + ks*32);
                mma16816(sc[2*p],   aqh, kbh);
                mma16816(sc[2*p+1], aqh, kbh+2);
                mma16816(sc[2*p],   aql, kbh);
                mma16816(sc[2*p+1], aql, kbh+2);
            }
        }

        // ---- mask + online softmax ----
        const int qm0 = sMq[(w << 4) + g];
        const int qm1 = sMq[(w << 4) + g + 8];
        float mx0 = -1e30f, mx1 = -1e30f;
        #pragma unroll
        for (int nt = 0; nt < 4; nt++) {
            const int jb = (nt << 3) + (t << 1);
            const int k0 = sMk[jb], k1 = sMk[jb + 1];
            const int gj0 = j0 + jb, gj1 = gj0 + 1;
            sc[nt][0] = (qm0 && k0 && gj0 <= gi0) ? sc[nt][0] * 0.0625f : -1e30f;
            sc[nt][1] = (qm0 && k1 && gj1 <= gi0) ? sc[nt][1] * 0.0625f : -1e30f;
            sc[nt][2] = (qm1 && k0 && gj0 <= gi1) ? sc[nt][2] * 0.0625f : -1e30f;
            sc[nt][3] = (qm1 && k1 && gj1 <= gi1) ? sc[nt][3] * 0.0625f : -1e30f;
            mx0 = fmaxf(mx0, fmaxf(sc[nt][0], sc[nt][1]));
            mx1 = fmaxf(mx1, fmaxf(sc[nt][2], sc[nt][3]));
        }
        mx0 = fmaxf(mx0, __shfl_xor_sync(0xffffffffu, mx0, 1, 4));
        mx0 = fmaxf(mx0, __shfl_xor_sync(0xffffffffu, mx0, 2, 4));
        mx1 = fmaxf(mx1, __shfl_xor_sync(0xffffffffu, mx1, 1, 4));
        mx1 = fmaxf(mx1, __shfl_xor_sync(0xffffffffu, mx1, 2, 4));

        const float mn0 = fmaxf(m_run0, mx0);
        const float mn1 = fmaxf(m_run1, mx1);
        const float al0 = exp2f((m_run0 - mn0) * L2E);
        const float al1 = exp2f((m_run1 - mn1) * L2E);
        m_run0 = mn0; m_run1 = mn1;

        float ps0 = 0.f, ps1 = 0.f;
        #pragma unroll
        for (int nt = 0; nt < 4; nt++) {
            float p0 = exp2f((sc[nt][0] - mn0) * L2E);
            float p1 = exp2f((sc[nt][1] - mn0) * L2E);
            float p2 = exp2f((sc[nt][2] - mn1) * L2E);
            float p3 = exp2f((sc[nt][3] - mn1) * L2E);
            sc[nt][0] = p0; sc[nt][1] = p1; sc[nt][2] = p2; sc[nt][3] = p3;
            ps0 += p0 + p1; ps1 += p2 + p3;
        }
        ps0 += __shfl_xor_sync(0xffffffffu, ps0, 1, 4);
        ps0 += __shfl_xor_sync(0xffffffffu, ps0, 2, 4);
        ps1 += __shfl_xor_sync(0xffffffffu, ps1, 1, 4);
        ps1 += __shfl_xor_sync(0xffffffffu, ps1, 2, 4);
        l_run0 = l_run0 * al0 + ps0;
        l_run1 = l_run1 * al1 + ps1;

        const bool skip = __all_sync(0xffffffffu, (al0 == 1.f) && (al1 == 1.f));
        if (!skip) {
            #pragma unroll
            for (int i = 0; i < 32; i++) {
                accO[i][0] *= al0; accO[i][1] *= al0;
                accO[i][2] *= al1; accO[i][3] *= al1;
            }
        }

        // ---- O += (Ph+Pl)·Vh ----
        #pragma unroll
        for (int ks = 0; ks < 2; ks++) {
            unsigned aPh[4], aPl[4];
            packsplit(sc[2*ks][0],   sc[2*ks][1],   aPh[0], aPl[0]);
            packsplit(sc[2*ks][2],   sc[2*ks][3],   aPh[1], aPl[1]);
            packsplit(sc[2*ks+1][0], sc[2*ks+1][1], aPh[2], aPl[2]);
            packsplit(sc[2*ks+1][2], sc[2*ks+1][3], aPh[3], aPl[3]);
            #pragma unroll
            for (int nv = 0; nv < 16; nv++) {
                unsigned vbh[4];
                ldsm4t(vbh, bVh + offV + ks*(16*QS*2) + nv*32);
                mma16816(accO[2*nv],   aPh, vbh);
                mma16816(accO[2*nv+1], aPh, vbh+2);
                mma16816(accO[2*nv],   aPl, vbh);
                mma16816(accO[2*nv+1], aPl, vbh+2);
            }
        }
    }

    // ---- epilogue ----
    const int qm0 = sMq[(w << 4) + g];
    const int qm1 = sMq[(w << 4) + g + 8];
    const float inv0 = (qm0 && l_run0 > 0.f) ? (1.f / l_run0) : 0.f;
    const float inv1 = (qm1 && l_run1 > 0.f) ? (1.f / l_run1) : 0.f;
    const size_t o0 = (size_t)(b * SEQ + gi0) * (NH * HD) + h * HD;
    const size_t o1 = (size_t)(b * SEQ + gi1) * (NH * HD) + h * HD;
    #pragma unroll
    for (int nt = 0; nt < 32; nt++) {
        const int col = (nt << 3) + (t << 1);
        unsigned h0, l0, h1, l1;
        packsplit(accO[nt][0] * inv0, accO[nt][1] * inv0, h0, l0);
        packsplit(accO[nt][2] * inv1, accO[nt][3] * inv1, h1, l1);
        *(unsigned*)(atth + o0 + col) = h0;
        *(unsigned*)(attl + o0 + col) = l0;
        *(unsigned*)(atth + o1 + col) = h1;
        *(unsigned*)(attl + o1 + col) = l1;
    }
}

// ---------------- fused residual-add + LayerNorm ----------------
template<int SPLIT>
__global__ __launch_bounds__(256) void add_ln_kernel(
    const float* __restrict__ a, const float* __restrict__ b2,
    const float* __restrict__ g, const float* __restrict__ be,
    float* __restrict__ out,
    __half* __restrict__ oh, __half* __restrict__ ol)
{
    __shared__ float red[16];
    const int row = blockIdx.x, t = threadIdx.x;
    const size_t off = (size_t)row * HD + t;
    const float v = a[off] + b2[off];
    float sv = v, sq = v * v;
    #pragma unroll
    for (int o = 16; o; o >>= 1) {
        sv += __shfl_xor_sync(0xffffffffu, sv, o);
        sq += __shfl_xor_sync(0xffffffffu, sq, o);
    }
    if ((t & 31) == 0) { red[t >> 5] = sv; red[8 + (t >> 5)] = sq; }
    __syncthreads();
    if (t == 0) {
        float s1 = 0.f, s2 = 0.f;
        #pragma unroll
        for (int i = 0; i < 8; i++) { s1 += red[i]; s2 += red[8 + i]; }
        red[0] = s1; red[8] = s2;
    }
    __syncthreads();
    const float mu  = red[0] * (1.f / 256.f);
    const float var = red[8] * (1.f / 256.f) - mu * mu;
    const float r = (v - mu) * rsqrtf(var + 1e-5f) * g[t] + be[t];
    out[off] = r;
    if (SPLIT) {
        __half hi = __float2half_rn(r);
        oh[off] = hi;
        ol[off] = __float2half_rn(r - __half2float(hi));
    }
}

// ---------------- launch ----------------
extern "C" void kernel_launch(void* const* d_in, const int* in_sizes, int n_in,
                              void* d_out, int out_size)
{
    const float* x    = (const float*)d_in[0];
    const int*   am   = (const int*  )d_in[1];
    const float* wq   = (const float*)d_in[2];
    const float* wk   = (const float*)d_in[3];
    const float* wv   = (const float*)d_in[4];
    const float* wo_w = (const float*)d_in[5];
    const float* wo_b = (const float*)d_in[6];
    const float* ln1g = (const float*)d_in[7];
    const float* ln1b = (const float*)d_in[8];
    const float* f1w  = (const float*)d_in[9];
    const float* f1b  = (const float*)d_in[10];
    const float* f2w  = (const float*)d_in[11];
    const float* f2b  = (const float*)d_in[12];
    const float* ln2g = (const float*)d_in[13];
    const float* ln2b = (const float*)d_in[14];
    float* out = (float*)d_out;
    (void)in_sizes; (void)n_in; (void)out_size;

    __half *pxh, *pxl, *pwh, *pwl, *pqh, *pql, *pkh, *pkl, *pvh, *pvl;
    __half *path, *patl, *px1h, *px1l, *phh, *phl;
    float *px1, *pt1;
    cudaGetSymbolAddress((void**)&pxh, g_xh);
    cudaGetSymbolAddress((void**)&pxl, g_xl);
    cudaGetSymbolAddress((void**)&pwh, g_wh);
    cudaGetSymbolAddress((void**)&pwl, g_wl);
    cudaGetSymbolAddress((void**)&pqh, g_qh);
    cudaGetSymbolAddress((void**)&pql, g_ql);
    cudaGetSymbolAddress((void**)&pkh, g_kh);
    cudaGetSymbolAddress((void**)&pkl, g_kl);
    cudaGetSymbolAddress((void**)&pvh, g_vh);
    cudaGetSymbolAddress((void**)&pvl, g_vl);
    cudaGetSymbolAddress((void**)&path, g_ath);
    cudaGetSymbolAddress((void**)&patl, g_atl);
    cudaGetSymbolAddress((void**)&px1h, g_x1h);
    cudaGetSymbolAddress((void**)&px1l, g_x1l);
    cudaGetSymbolAddress((void**)&phh, g_hh);
    cudaGetSymbolAddress((void**)&phl, g_hl);
    cudaGetSymbolAddress((void**)&px1, g_x1);
    cudaGetSymbolAddress((void**)&pt1, g_t1);

    cudaFuncSetAttribute(gemm_qkv_kernel, cudaFuncAttributeMaxDynamicSharedMemorySize, GEMM_SMEM);
    cudaFuncSetAttribute(gemm_kernel<0>,  cudaFuncAttributeMaxDynamicSharedMemorySize, GEMM_SMEM);
    cudaFuncSetAttribute(gemm_kernel<3>,  cudaFuncAttributeMaxDynamicSharedMemorySize, GEMM_SMEM);
    cudaFuncSetAttribute(flash_mma_kernel, cudaFuncAttributeMaxDynamicSharedMemorySize, FLASH_SMEM);

    // ---- pre-split x and weights ----
    split_x_kernel<<<MTOK*HD/1024, 256>>>(x, pxh, pxl);
    split_w_kernel<<<WTOT/1024, 256>>>(wq, wk, wv, wo_w, f1w, f2w, pwh, pwl);

    // ---- QKV projections ----
    gemm_qkv_kernel<<<dim3(HD/128, MTOK/128, 12), 256, GEMM_SMEM>>>(
        pxh, pxl, pwh, pwl, pqh, pql, pkh, pkl, pvh, pvl);

    // ---- causal flash attention (v7: fp16, K/V hi-only) ----
    flash_mma_kernel<<<dim3(SEQ/128, BATCH*NH), 256, FLASH_SMEM>>>(
        pqh, pql, pkh, pvh, am, path, patl);

    // ---- output projection + residual/LN1 ----
    gemm_kernel<0><<<dim3(HD/128, MTOK/128), 256, GEMM_SMEM>>>(
        path, patl, pwh + WOFF_O, pwl + WOFF_O, wo_b, pt1, nullptr, nullptr, HD, NH*HD);
    add_ln_kernel<1><<<MTOK, 256>>>(x, pt1, ln1g, ln1b, px1, px1h, px1l);

    // ---- FFN ----
    gemm_kernel<3><<<dim3(FF/128, MTOK/128), 256, GEMM_SMEM>>>(
        px1h, px1l, pwh + WOFF_F1, pwl + WOFF_F1, f1b, nullptr, phh, phl, FF, HD);
    gemm_kernel<0><<<dim3(HD/128, MTOK/128), 256, GEMM_SMEM>>>(
        phh, phl, pwh + WOFF_F2, pwl + WOFF_F2, f2b, pt1, nullptr, nullptr, HD, FF);
    add_ln_kernel<0><<<MTOK, 256>>>(px1, pt1, ln2g, ln2b, out, nullptr, nullptr);
}

// round 15
// speedup vs baseline: 1.4999x; 1.1914x over previous
#include <cuda_runtime.h>
#include <cuda_fp16.h>
#include <math.h>
#include <stdint.h>

// ---------------- problem constants ----------------
#define NH    4
#define HD    256
#define SEQ   1024
#define BATCH 8
#define MTOK  (BATCH*SEQ)
#define FF    1024

#define WOFF_Q  0
#define WOFF_K  262144
#define WOFF_V  524288
#define WOFF_O  786432
#define WOFF_F1 1048576
#define WOFF_F2 1310720
#define WTOT    1572864

// ---------------- scratch (fp16 split world) ----------------
__device__ __align__(16) __half g_xh [(size_t)MTOK*HD];
__device__ __align__(16) __half g_xl [(size_t)MTOK*HD];
__device__ __align__(16) __half g_wh [(size_t)WTOT];
__device__ __align__(16) __half g_qh [(size_t)NH*MTOK*HD];
__device__ __align__(16) __half g_ql [(size_t)NH*MTOK*HD];
__device__ __align__(16) __half g_kh [(size_t)NH*MTOK*HD];
__device__ __align__(16) __half g_vh [(size_t)NH*MTOK*HD];
__device__ __align__(16) __half g_ath[(size_t)MTOK*NH*HD];
__device__ __align__(16) __half g_atl[(size_t)MTOK*NH*HD];
__device__ __align__(16) __half g_x1h[(size_t)MTOK*HD];
__device__ __align__(16) __half g_x1l[(size_t)MTOK*HD];
__device__ __align__(16) __half g_hh [(size_t)MTOK*FF];
__device__ __align__(16) __half g_hl [(size_t)MTOK*FF];
__device__ float g_x1 [(size_t)MTOK*HD];
__device__ float g_t1 [(size_t)MTOK*HD];

// ---------------- helpers ----------------
__device__ __forceinline__ void packsplit(float a, float b, unsigned& hi, unsigned& lo)
{
    __half ah = __float2half_rn(a);
    __half bh = __float2half_rn(b);
    __half2 h = __halves2half2(ah, bh);
    __half2 l = __floats2half2_rn(a - __half2float(ah), b - __half2float(bh));
    hi = *reinterpret_cast<unsigned*>(&h);
    lo = *reinterpret_cast<unsigned*>(&l);
}

__device__ __forceinline__ void split8(__half* hi_p, __half* lo_p, float4 v)
{
    unsigned h01, l01, h23, l23;
    packsplit(v.x, v.y, h01, l01);
    packsplit(v.z, v.w, h23, l23);
    *reinterpret_cast<uint2*>(hi_p) = make_uint2(h01, h23);
    *reinterpret_cast<uint2*>(lo_p) = make_uint2(l01, l23);
}

__device__ __forceinline__ void pack8hi(__half* hi_p, float4 v)
{
    __half2 h01 = __floats2half2_rn(v.x, v.y);
    __half2 h23 = __floats2half2_rn(v.z, v.w);
    *reinterpret_cast<uint2*>(hi_p) =
        make_uint2(*reinterpret_cast<unsigned*>(&h01), *reinterpret_cast<unsigned*>(&h23));
}

__device__ __forceinline__ void mma16816(float* c, const unsigned* a, const unsigned* b)
{
    asm volatile(
        "mma.sync.aligned.m16n8k16.row.col.f32.f16.f16.f32 "
        "{%0,%1,%2,%3}, {%4,%5,%6,%7}, {%8,%9}, {%0,%1,%2,%3};\n"
        : "+f"(c[0]), "+f"(c[1]), "+f"(c[2]), "+f"(c[3])
        : "r"(a[0]), "r"(a[1]), "r"(a[2]), "r"(a[3]), "r"(b[0]), "r"(b[1]));
}

__device__ __forceinline__ void ldsm4(unsigned* d, unsigned addr)
{
    asm volatile("ldmatrix.sync.aligned.m8n8.x4.shared.b16 {%0,%1,%2,%3}, [%4];"
                 : "=r"(d[0]), "=r"(d[1]), "=r"(d[2]), "=r"(d[3]) : "r"(addr));
}

__device__ __forceinline__ void ldsm4t(unsigned* d, unsigned addr)
{
    asm volatile("ldmatrix.sync.aligned.m8n8.x4.trans.shared.b16 {%0,%1,%2,%3}, [%4];"
                 : "=r"(d[0]), "=r"(d[1]), "=r"(d[2]), "=r"(d[3]) : "r"(addr));
}

__device__ __forceinline__ void cpasync16(unsigned dst, const void* src)
{
    asm volatile("cp.async.cg.shared.global [%0], [%1], 16;" :: "r"(dst), "l"(src));
}
__device__ __forceinline__ void cpcommit()
{
    asm volatile("cp.async.commit_group;" ::: "memory");
}
template<int N>
__device__ __forceinline__ void cpwait()
{
    asm volatile("cp.async.wait_group %0;" :: "n"(N) : "memory");
}

// ---------------- pre-split kernels ----------------
__global__ __launch_bounds__(256) void split_x_kernel(
    const float* __restrict__ x, __half* __restrict__ oh, __half* __restrict__ ol)
{
    const size_t e = ((size_t)blockIdx.x * 256 + threadIdx.x) * 4;
    if (e >= (size_t)MTOK * HD) return;
    split8(oh + e, ol + e, *(const float4*)(x + e));
}

__global__ __launch_bounds__(256) void split_w_kernel(
    const float* __restrict__ wq, const float* __restrict__ wk, const float* __restrict__ wv,
    const float* __restrict__ wo, const float* __restrict__ f1, const float* __restrict__ f2,
    __half* __restrict__ oh)
{
    const size_t e = ((size_t)blockIdx.x * 256 + threadIdx.x) * 4;
    if (e >= (size_t)WTOT) return;
    const float* src; size_t off;
    if      (e < WOFF_K)  { src = wq; off = WOFF_Q;  }
    else if (e < WOFF_V)  { src = wk; off = WOFF_K;  }
    else if (e < WOFF_O)  { src = wv; off = WOFF_V;  }
    else if (e < WOFF_F1) { src = wo; off = WOFF_O;  }
    else if (e < WOFF_F2) { src = f1; off = WOFF_F1; }
    else                  { src = f2; off = WOFF_F2; }
    pack8hi(oh + e, *(const float4*)(src + (e - off)));
}

// =================================================================
// fp16x2 GEMM: A split (hi/lo), B (weights) fp16 hi-only.
// MODE bit0=relu, bit1=split fp16 out, bit2=suppress lo stores.
// =================================================================
#define ASTR 40
#define BOFF (2*2*128*ASTR)
#define GEMM_SMEM ((2*2 + 2)*128*ASTR*2)   // 61440 B

template<int MODE>
__device__ __forceinline__ void gemm_core(
    const __half* __restrict__ Ah, const __half* __restrict__ Al,
    const __half* __restrict__ Bh,
    const float* __restrict__ bias, float* __restrict__ C,
    __half* __restrict__ Chi, __half* __restrict__ Clo,
    int N, int K, int m0, int n0)
{
    extern __shared__ __half sm_bf[];
    const unsigned sbase = (unsigned)__cvta_generic_to_shared(sm_bf);

    const int tid  = threadIdx.x;
    const int lane = tid & 31, warp = tid >> 5;
    const int wm = (warp >> 2) << 6;
    const int wn = (warp & 3)  << 5;
    const int g = lane >> 2, t = lane & 3;
    const int KT = K >> 5;

    const __half* Agh = Ah + (size_t)m0 * K;
    const __half* Agl = Al + (size_t)m0 * K;
    const __half* Bgh = Bh + (size_t)n0 * K;

    const int sr = tid >> 2;
    const int scol = (tid & 3) << 3;

    float acc[4][4][4];
    #pragma unroll
    for (int i = 0; i < 4; i++)
        #pragma unroll
        for (int j = 0; j < 4; j++)
            #pragma unroll
            for (int q = 0; q < 4; q++) acc[i][j][q] = 0.f;

    const int arow = lane & 15;
    const int acol = (lane >> 4) << 3;
    const int brow = (lane & 7) | ((lane >> 1) & 8);
    const int bcol = lane & 8;

    {
        #pragma unroll
        for (int i = 0; i < 2; i++) {
            const int r = (i << 6) + sr;
            cpasync16(sbase + (unsigned)(((0*2 + 0)*128 + r)*ASTR + scol) * 2,
                      Agh + (size_t)r * K + scol);
            cpasync16(sbase + (unsigned)(((0*2 + 1)*128 + r)*ASTR + scol) * 2,
                      Agl + (size_t)r * K + scol);
            cpasync16(sbase + (unsigned)((BOFF + (0*128 + r)*ASTR + scol)) * 2,
                      Bgh + (size_t)r * K + scol);
        }
        cpcommit();
    }

    for (int kt = 0; kt < KT; kt++) {
        const int buf = kt & 1;
        if (kt + 1 < KT) {
            const int ko = (kt + 1) << 5;
            const int nb = buf ^ 1;
            #pragma unroll
            for (int i = 0; i < 2; i++) {
                const int r = (i << 6) + sr;
                cpasync16(sbase + (unsigned)(((nb*2 + 0)*128 + r)*ASTR + scol) * 2,
                          Agh + (size_t)r * K + ko + scol);
                cpasync16(sbase + (unsigned)(((nb*2 + 1)*128 + r)*ASTR + scol) * 2,
                          Agl + (size_t)r * K + ko + scol);
                cpasync16(sbase + (unsigned)((BOFF + (nb*128 + r)*ASTR + scol)) * 2,
                          Bgh + (size_t)r * K + ko + scol);
            }
            cpcommit();
            cpwait<1>();
        } else {
            cpwait<0>();
        }
        __syncthreads();

        const unsigned aHi = sbase + (unsigned)((buf*2 + 0)*128*ASTR) * 2;
        const unsigned aLo = sbase + (unsigned)((buf*2 + 1)*128*ASTR) * 2;
        const unsigned bHi = sbase + (unsigned)((BOFF + buf*128*ASTR)) * 2;

        #pragma unroll
        for (int ks = 0; ks < 2; ks++) {
            const int kc = ks << 4;
            unsigned bh[2][4];
            #pragma unroll
            for (int np = 0; np < 2; np++) {
                const unsigned bo = (unsigned)((wn + (np << 4) + brow)*ASTR + kc + bcol) * 2;
                ldsm4(bh[np], bHi + bo);
            }
            #pragma unroll
            for (int mh = 0; mh < 2; mh++) {
                unsigned ah[2][4], al[2][4];
                #pragma unroll
                for (int m2 = 0; m2 < 2; m2++) {
                    const unsigned ao = (unsigned)((wm + ((mh*2 + m2) << 4) + arow)*ASTR + kc + acol) * 2;
                    ldsm4(ah[m2], aHi + ao);
                    ldsm4(al[m2], aLo + ao);
                }
                #pragma unroll
                for (int m2 = 0; m2 < 2; m2++) {
                    #pragma unroll
                    for (int nt = 0; nt < 4; nt++)
                        mma16816(acc[mh*2 + m2][nt], ah[m2], bh[nt >> 1] + ((nt & 1) << 1));
                    #pragma unroll
                    for (int nt = 0; nt < 4; nt++)
                        mma16816(acc[mh*2 + m2][nt], al[m2], bh[nt >> 1] + ((nt & 1) << 1));
                }
            }
        }
        __syncthreads();
    }

    #pragma unroll
    for (int mt = 0; mt < 4; mt++) {
        const int row = m0 + wm + (mt << 4) + g;
        #pragma unroll
        for (int nt = 0; nt < 4; nt++) {
            const int col = n0 + wn + (nt << 3) + (t << 1);
            float bx = 0.f, by = 0.f;
            if (bias) { bx = bias[col]; by = bias[col + 1]; }
            float v0 = acc[mt][nt][0] + bx, v1 = acc[mt][nt][1] + by;
            float v2 = acc[mt][nt][2] + bx, v3 = acc[mt][nt][3] + by;
            if (MODE & 1) {
                v0 = fmaxf(v0, 0.f); v1 = fmaxf(v1, 0.f);
                v2 = fmaxf(v2, 0.f); v3 = fmaxf(v3, 0.f);
            }
            if (MODE & 2) {
                unsigned h01, l01, h23, l23;
                packsplit(v0, v1, h01, l01);
                packsplit(v2, v3, h23, l23);
                *(unsigned*)(Chi + (size_t)row * N + col)       = h01;
                *(unsigned*)(Chi + (size_t)(row + 8) * N + col) = h23;
                if (!(MODE & 4)) {
                    *(unsigned*)(Clo + (size_t)row * N + col)       = l01;
                    *(unsigned*)(Clo + (size_t)(row + 8) * N + col) = l23;
                }
            } else {
                *(float2*)(C + (size_t)row * N + col)       = make_float2(v0, v1);
                *(float2*)(C + (size_t)(row + 8) * N + col) = make_float2(v2, v3);
            }
        }
    }
}

template<int MODE>
__global__ __launch_bounds__(256, 2) void gemm_kernel(
    const __half* __restrict__ Ah, const __half* __restrict__ Al,
    const __half* __restrict__ Bh,
    const float* __restrict__ bias, float* __restrict__ C,
    __half* __restrict__ Chi, __half* __restrict__ Clo, int N, int K)
{
    gemm_core<MODE>(Ah, Al, Bh, bias, C, Chi, Clo, N, K,
                    blockIdx.y << 7, blockIdx.x << 7);
}

__global__ __launch_bounds__(256, 2) void gemm_qkv_kernel(
    const __half* __restrict__ xh, const __half* __restrict__ xl,
    const __half* __restrict__ wh,
    __half* __restrict__ qh, __half* __restrict__ ql,
    __half* __restrict__ kh, __half* __restrict__ vh)
{
    const int z = blockIdx.z;
    const int mat = z >> 2, h = z & 3;
    const size_t woff = (size_t)mat * 262144 + (size_t)h * 65536;
    if (mat == 0) {
        gemm_core<2>(xh, xl, wh + woff, nullptr, nullptr,
                     qh + (size_t)h * MTOK * HD, ql + (size_t)h * MTOK * HD,
                     HD, HD, blockIdx.y << 7, blockIdx.x << 7);
    } else {
        __half* Chi = (mat == 1 ? kh : vh) + (size_t)h * MTOK * HD;
        gemm_core<6>(xh, xl, wh + woff, nullptr, nullptr,
                     Chi, nullptr, HD, HD, blockIdx.y << 7, blockIdx.x << 7);
    }
}

// =================================================================
// flash v7 (unchanged from R14 winner)
// =================================================================
#define QS 264
#define FLASH_SMEM ((2*128 + 2*32)*QS*2)
#define L2E 1.4426950408889634f

__global__ __launch_bounds__(256, 1) void flash_mma_kernel(
    const __half* __restrict__ qh, const __half* __restrict__ ql,
    const __half* __restrict__ kh, const __half* __restrict__ vh,
    const int* __restrict__ amask,
    __half* __restrict__ atth, __half* __restrict__ attl)
{
    extern __shared__ __half sm[];
    __half* sQh = sm;
    __half* sQl = sQh + 128*QS;
    __half* sKh = sQl + 128*QS;
    __half* sVh = sKh + 32*QS;
    __shared__ int sMq[128];
    __shared__ int sMk[32];

    const int tid  = threadIdx.x;
    const int lane = tid & 31, w = tid >> 5;
    const int g = lane >> 2, t = lane & 3;
    const int bh = blockIdx.y;
    const int b = bh >> 2, h = bh & 3;
    const int qidx = (int)gridDim.x - 1 - (int)blockIdx.x;
    const int m0 = qidx << 7;
    const size_t base = ((size_t)h * MTOK + (size_t)b * SEQ) * HD;

    const unsigned bQh = (unsigned)__cvta_generic_to_shared(sQh);
    const unsigned bQl = (unsigned)__cvta_generic_to_shared(sQl);
    const unsigned bKh = (unsigned)__cvta_generic_to_shared(sKh);
    const unsigned bVh = (unsigned)__cvta_generic_to_shared(sVh);

    const unsigned offA = (((w << 4) + (lane & 15)) * QS + ((lane >> 4) << 3)) * 2;
    const unsigned offB = ((((lane & 7) | ((lane >> 1) & 8)) * QS) + (lane & 8)) * 2;
    const unsigned offV = (((lane & 15) * QS) + ((lane >> 4) << 3)) * 2;

    {
        const __half* Qh = qh + base + (size_t)m0 * HD;
        const __half* Ql = ql + base + (size_t)m0 * HD;
        for (int i = tid; i < 4096; i += 256) {
            int r = i >> 5, c = (i & 31) << 3;
            cpasync16(bQh + (unsigned)(r*QS + c)*2, Qh + (size_t)r*HD + c);
            cpasync16(bQl + (unsigned)(r*QS + c)*2, Ql + (size_t)r*HD + c);
        }
        if (tid < 128) sMq[tid] = amask[b * SEQ + m0 + tid];
    }

    float accO[32][4];
    #pragma unroll
    for (int i = 0; i < 32; i++)
        #pragma unroll
        for (int j = 0; j < 4; j++) accO[i][j] = 0.f;
    float m_run0 = -1e30f, m_run1 = -1e30f, l_run0 = 0.f, l_run1 = 0.f;

    const int gi0 = m0 + (w << 4) + g;
    const int gi1 = gi0 + 8;

    const int ntiles = (qidx + 1) << 2;
    for (int kt = 0; kt < ntiles; kt++) {
        const int j0 = kt << 5;
        __syncthreads();
        {
            const __half* Kh = kh + base + (size_t)j0 * HD;
            const __half* Vh = vh + base + (size_t)j0 * HD;
            for (int i = tid; i < 1024; i += 256) {
                int r = i >> 5, c = (i & 31) << 3;
                const unsigned so = (unsigned)(r*QS + c) * 2;
                const size_t go = (size_t)r*HD + c;
                cpasync16(bKh + so, Kh + go);
                cpasync16(bVh + so, Vh + go);
            }
            if (tid < 32) sMk[tid] = amask[b * SEQ + j0 + tid];
            cpcommit();
            cpwait<0>();
        }
        __syncthreads();

        float sc[4][4];
        #pragma unroll
        for (int i = 0; i < 4; i++)
            #pragma unroll
            for (int j = 0; j < 4; j++) sc[i][j] = 0.f;

        #pragma unroll 4
        for (int ks = 0; ks < 16; ks++) {
            unsigned aqh[4], aql[4];
            ldsm4(aqh, bQh + offA + ks*32);
            ldsm4(aql, bQl + offA + ks*32);
            #pragma unroll
            for (int p = 0; p < 2; p++) {
                unsigned kbh[4];
                ldsm4(kbh, bKh + offB + p*(16*QS*2) + ks*32);
                mma16816(sc[2*p],   aqh, kbh);
                mma16816(sc[2*p+1], aqh, kbh+2);
                mma16816(sc[2*p],   aql, kbh);
                mma16816(sc[2*p+1], aql, kbh+2);
            }
        }

        const int qm0 = sMq[(w << 4) + g];
        const int qm1 = sMq[(w << 4) + g + 8];
        float mx0 = -1e30f, mx1 = -1e30f;
        #pragma unroll
        for (int nt = 0; nt < 4; nt++) {
            const int jb = (nt << 3) + (t << 1);
            const int k0 = sMk[jb], k1 = sMk[jb + 1];
            const int gj0 = j0 + jb, gj1 = gj0 + 1;
            sc[nt][0] = (qm0 && k0 && gj0 <= gi0) ? sc[nt][0] * 0.0625f : -1e30f;
            sc[nt][1] = (qm0 && k1 && gj1 <= gi0) ? sc[nt][1] * 0.0625f : -1e30f;
            sc[nt][2] = (qm1 && k0 && gj0 <= gi1) ? sc[nt][2] * 0.0625f : -1e30f;
            sc[nt][3] = (qm1 && k1 && gj1 <= gi1) ? sc[nt][3] * 0.0625f : -1e30f;
            mx0 = fmaxf(mx0, fmaxf(sc[nt][0], sc[nt][1]));
            mx1 = fmaxf(mx1, fmaxf(sc[nt][2], sc[nt][3]));
        }
        mx0 = fmaxf(mx0, __shfl_xor_sync(0xffffffffu, mx0, 1, 4));
        mx0 = fmaxf(mx0, __shfl_xor_sync(0xffffffffu, mx0, 2, 4));
        mx1 = fmaxf(mx1, __shfl_xor_sync(0xffffffffu, mx1, 1, 4));
        mx1 = fmaxf(mx1, __shfl_xor_sync(0xffffffffu, mx1, 2, 4));

        const float mn0 = fmaxf(m_run0, mx0);
        const float mn1 = fmaxf(m_run1, mx1);
        const float al0 = exp2f((m_run0 - mn0) * L2E);
        const float al1 = exp2f((m_run1 - mn1) * L2E);
        m_run0 = mn0; m_run1 = mn1;

        float ps0 = 0.f, ps1 = 0.f;
        #pragma unroll
        for (int nt = 0; nt < 4; nt++) {
            float p0 = exp2f((sc[nt][0] - mn0) * L2E);
            float p1 = exp2f((sc[nt][1] - mn0) * L2E);
            float p2 = exp2f((sc[nt][2] - mn1) * L2E);
            float p3 = exp2f((sc[nt][3] - mn1) * L2E);
            sc[nt][0] = p0; sc[nt][1] = p1; sc[nt][2] = p2; sc[nt][3] = p3;
            ps0 += p0 + p1; ps1 += p2 + p3;
        }
        ps0 += __shfl_xor_sync(0xffffffffu, ps0, 1, 4);
        ps0 += __shfl_xor_sync(0xffffffffu, ps0, 2, 4);
        ps1 += __shfl_xor_sync(0xffffffffu, ps1, 1, 4);
        ps1 += __shfl_xor_sync(0xffffffffu, ps1, 2, 4);
        l_run0 = l_run0 * al0 + ps0;
        l_run1 = l_run1 * al1 + ps1;

        const bool skip = __all_sync(0xffffffffu, (al0 == 1.f) && (al1 == 1.f));
        if (!skip) {
            #pragma unroll
            for (int i = 0; i < 32; i++) {
                accO[i][0] *= al0; accO[i][1] *= al0;
                accO[i][2] *= al1; accO[i][3] *= al1;
            }
        }

        #pragma unroll
        for (int ks = 0; ks < 2; ks++) {
            unsigned aPh[4], aPl[4];
            packsplit(sc[2*ks][0],   sc[2*ks][1],   aPh[0], aPl[0]);
            packsplit(sc[2*ks][2],   sc[2*ks][3],   aPh[1], aPl[1]);
            packsplit(sc[2*ks+1][0], sc[2*ks+1][1], aPh[2], aPl[2]);
            packsplit(sc[2*ks+1][2], sc[2*ks+1][3], aPh[3], aPl[3]);
            #pragma unroll
            for (int nv = 0; nv < 16; nv++) {
                unsigned vbh[4];
                ldsm4t(vbh, bVh + offV + ks*(16*QS*2) + nv*32);
                mma16816(accO[2*nv],   aPh, vbh);
                mma16816(accO[2*nv+1], aPh, vbh+2);
                mma16816(accO[2*nv],   aPl, vbh);
                mma16816(accO[2*nv+1], aPl, vbh+2);
            }
        }
    }

    const int qm0 = sMq[(w << 4) + g];
    const int qm1 = sMq[(w << 4) + g + 8];
    const float inv0 = (qm0 && l_run0 > 0.f) ? (1.f / l_run0) : 0.f;
    const float inv1 = (qm1 && l_run1 > 0.f) ? (1.f / l_run1) : 0.f;
    const size_t o0 = (size_t)(b * SEQ + gi0) * (NH * HD) + h * HD;
    const size_t o1 = (size_t)(b * SEQ + gi1) * (NH * HD) + h * HD;
    #pragma unroll
    for (int nt = 0; nt < 32; nt++) {
        const int col = (nt << 3) + (t << 1);
        unsigned h0, l0, h1, l1;
        packsplit(accO[nt][0] * inv0, accO[nt][1] * inv0, h0, l0);
        packsplit(accO[nt][2] * inv1, accO[nt][3] * inv1, h1, l1);
        *(unsigned*)(atth + o0 + col) = h0;
        *(unsigned*)(attl + o0 + col) = l0;
        *(unsigned*)(atth + o1 + col) = h1;
        *(unsigned*)(attl + o1 + col) = l1;
    }
}

// ---------------- fused residual-add + LayerNorm ----------------
template<int SPLIT>
__global__ __launch_bounds__(256) void add_ln_kernel(
    const float* __restrict__ a, const float* __restrict__ b2,
    const float* __restrict__ g, const float* __restrict__ be,
    float* __restrict__ out,
    __half* __restrict__ oh, __half* __restrict__ ol)
{
    __shared__ float red[16];
    const int row = blockIdx.x, t = threadIdx.x;
    const size_t off = (size_t)row * HD + t;
    const float v = a[off] + b2[off];
    float sv = v, sq = v * v;
    #pragma unroll
    for (int o = 16; o; o >>= 1) {
        sv += __shfl_xor_sync(0xffffffffu, sv, o);
        sq += __shfl_xor_sync(0xffffffffu, sq, o);
    }
    if ((t & 31) == 0) { red[t >> 5] = sv; red[8 + (t >> 5)] = sq; }
    __syncthreads();
    if (t == 0) {
        float s1 = 0.f, s2 = 0.f;
        #pragma unroll
        for (int i = 0; i < 8; i++) { s1 += red[i]; s2 += red[8 + i]; }
        red[0] = s1; red[8] = s2;
    }
    __syncthreads();
    const float mu  = red[0] * (1.f / 256.f);
    const float var = red[8] * (1.f / 256.f) - mu * mu;
    const float r = (v - mu) * rsqrtf(var + 1e-5f) * g[t] + be[t];
    out[off] = r;
    if (SPLIT) {
        __half hi = __float2half_rn(r);
        oh[off] = hi;
        ol[off] = __float2half_rn(r - __half2float(hi));
    }
}

// ---------------- launch ----------------
extern "C" void kernel_launch(void* const* d_in, const int* in_sizes, int n_in,
                              void* d_out, int out_size)
{
    const float* x    = (const float*)d_in[0];
    const int*   am   = (const int*  )d_in[1];
    const float* wq   = (const float*)d_in[2];
    const float* wk   = (const float*)d_in[3];
    const float* wv   = (const float*)d_in[4];
    const float* wo_w = (const float*)d_in[5];
    const float* wo_b = (const float*)d_in[6];
    const float* ln1g = (const float*)d_in[7];
    const float* ln1b = (const float*)d_in[8];
    const float* f1w  = (const float*)d_in[9];
    const float* f1b  = (const float*)d_in[10];
    const float* f2w  = (const float*)d_in[11];
    const float* f2b  = (const float*)d_in[12];
    const float* ln2g = (const float*)d_in[13];
    const float* ln2b = (const float*)d_in[14];
    float* out = (float*)d_out;
    (void)in_sizes; (void)n_in; (void)out_size;

    __half *pxh, *pxl, *pwh, *pqh, *pql, *pkh, *pvh;
    __half *path, *patl, *px1h, *px1l, *phh, *phl;
    float *px1, *pt1;
    cudaGetSymbolAddress((void**)&pxh, g_xh);
    cudaGetSymbolAddress((void**)&pxl, g_xl);
    cudaGetSymbolAddress((void**)&pwh, g_wh);
    cudaGetSymbolAddress((void**)&pqh, g_qh);
    cudaGetSymbolAddress((void**)&pql, g_ql);
    cudaGetSymbolAddress((void**)&pkh, g_kh);
    cudaGetSymbolAddress((void**)&pvh, g_vh);
    cudaGetSymbolAddress((void**)&path, g_ath);
    cudaGetSymbolAddress((void**)&patl, g_atl);
    cudaGetSymbolAddress((void**)&px1h, g_x1h);
    cudaGetSymbolAddress((void**)&px1l, g_x1l);
    cudaGetSymbolAddress((void**)&phh, g_hh);
    cudaGetSymbolAddress((void**)&phl, g_hl);
    cudaGetSymbolAddress((void**)&px1, g_x1);
    cudaGetSymbolAddress((void**)&pt1, g_t1);

    cudaFuncSetAttribute(gemm_qkv_kernel, cudaFuncAttributeMaxDynamicSharedMemorySize, GEMM_SMEM);
    cudaFuncSetAttribute(gemm_kernel<0>,  cudaFuncAttributeMaxDynamicSharedMemorySize, GEMM_SMEM);
    cudaFuncSetAttribute(gemm_kernel<3>,  cudaFuncAttributeMaxDynamicSharedMemorySize, GEMM_SMEM);
    cudaFuncSetAttribute(flash_mma_kernel, cudaFuncAttributeMaxDynamicSharedMemorySize, FLASH_SMEM);

    // ---- pre-split x; weights fp16 hi-only ----
    split_x_kernel<<<MTOK*HD/1024, 256>>>(x, pxh, pxl);
    split_w_kernel<<<WTOT/1024, 256>>>(wq, wk, wv, wo_w, f1w, f2w, pwh);

    // ---- QKV projections ----
    gemm_qkv_kernel<<<dim3(HD/128, MTOK/128, 12), 256, GEMM_SMEM>>>(
        pxh, pxl, pwh, pqh, pql, pkh, pvh);

    // ---- causal flash attention ----
    flash_mma_kernel<<<dim3(SEQ/128, BATCH*NH), 256, FLASH_SMEM>>>(
        pqh, pql, pkh, pvh, am, path, patl);

    // ---- output projection + residual/LN1 ----
    gemm_kernel<0><<<dim3(HD/128, MTOK/128), 256, GEMM_SMEM>>>(
        path, patl, pwh + WOFF_O, wo_b, pt1, nullptr, nullptr, HD, NH*HD);
    add_ln_kernel<1><<<MTOK, 256>>>(x, pt1, ln1g, ln1b, px1, px1h, px1l);

    // ---- FFN ----
    gemm_kernel<3><<<dim3(FF/128, MTOK/128), 256, GEMM_SMEM>>>(
        px1h, px1l, pwh + WOFF_F1, f1b, nullptr, phh, phl, FF, HD);
    gemm_kernel<0><<<dim3(HD/128, MTOK/128), 256, GEMM_SMEM>>>(
        phh, phl, pwh + WOFF_F2, f2b, pt1, nullptr, nullptr, HD, FF);
    add_ln_kernel<0><<<MTOK, 256>>>(px1, pt1, ln2g, ln2b, out, nullptr, nullptr);
}

// round 16
// speedup vs baseline: 1.7799x; 1.1866x over previous
#include <cuda_runtime.h>
#include <cuda_fp16.h>
#include <math.h>
#include <stdint.h>

// ---------------- problem constants ----------------
#define NH    4
#define HD    256
#define SEQ   1024
#define BATCH 8
#define MTOK  (BATCH*SEQ)
#define FF    1024

#define WOFF_Q  0
#define WOFF_K  262144
#define WOFF_V  524288
#define WOFF_O  786432
#define WOFF_F1 1048576
#define WOFF_F2 1310720
#define WTOT    1572864

// ---------------- scratch (fp16 world) ----------------
__device__ __align__(16) __half g_xh [(size_t)MTOK*HD];
__device__ __align__(16) __half g_xl [(size_t)MTOK*HD];
__device__ __align__(16) __half g_wh [(size_t)WTOT];
__device__ __align__(16) __half g_qh [(size_t)NH*MTOK*HD];
__device__ __align__(16) __half g_kh [(size_t)NH*MTOK*HD];
__device__ __align__(16) __half g_vh [(size_t)NH*MTOK*HD];
__device__ __align__(16) __half g_ath[(size_t)MTOK*NH*HD];
__device__ __align__(16) __half g_x1h[(size_t)MTOK*HD];
__device__ __align__(16) __half g_x1l[(size_t)MTOK*HD];
__device__ __align__(16) __half g_hh [(size_t)MTOK*FF];
__device__ __align__(16) __half g_hl [(size_t)MTOK*FF];
__device__ float g_x1 [(size_t)MTOK*HD];
__device__ float g_t1 [(size_t)MTOK*HD];

// ---------------- helpers ----------------
__device__ __forceinline__ void packsplit(float a, float b, unsigned& hi, unsigned& lo)
{
    __half ah = __float2half_rn(a);
    __half bh = __float2half_rn(b);
    __half2 h = __halves2half2(ah, bh);
    __half2 l = __floats2half2_rn(a - __half2float(ah), b - __half2float(bh));
    hi = *reinterpret_cast<unsigned*>(&h);
    lo = *reinterpret_cast<unsigned*>(&l);
}

__device__ __forceinline__ unsigned packhi(float a, float b)
{
    __half2 h = __floats2half2_rn(a, b);
    return *reinterpret_cast<unsigned*>(&h);
}

__device__ __forceinline__ void split8(__half* hi_p, __half* lo_p, float4 v)
{
    unsigned h01, l01, h23, l23;
    packsplit(v.x, v.y, h01, l01);
    packsplit(v.z, v.w, h23, l23);
    *reinterpret_cast<uint2*>(hi_p) = make_uint2(h01, h23);
    *reinterpret_cast<uint2*>(lo_p) = make_uint2(l01, l23);
}

__device__ __forceinline__ void pack8hi(__half* hi_p, float4 v)
{
    *reinterpret_cast<uint2*>(hi_p) = make_uint2(packhi(v.x, v.y), packhi(v.z, v.w));
}

__device__ __forceinline__ void mma16816(float* c, const unsigned* a, const unsigned* b)
{
    asm volatile(
        "mma.sync.aligned.m16n8k16.row.col.f32.f16.f16.f32 "
        "{%0,%1,%2,%3}, {%4,%5,%6,%7}, {%8,%9}, {%0,%1,%2,%3};\n"
        : "+f"(c[0]), "+f"(c[1]), "+f"(c[2]), "+f"(c[3])
        : "r"(a[0]), "r"(a[1]), "r"(a[2]), "r"(a[3]), "r"(b[0]), "r"(b[1]));
}

__device__ __forceinline__ void ldsm4(unsigned* d, unsigned addr)
{
    asm volatile("ldmatrix.sync.aligned.m8n8.x4.shared.b16 {%0,%1,%2,%3}, [%4];"
                 : "=r"(d[0]), "=r"(d[1]), "=r"(d[2]), "=r"(d[3]) : "r"(addr));
}

__device__ __forceinline__ void ldsm4t(unsigned* d, unsigned addr)
{
    asm volatile("ldmatrix.sync.aligned.m8n8.x4.trans.shared.b16 {%0,%1,%2,%3}, [%4];"
                 : "=r"(d[0]), "=r"(d[1]), "=r"(d[2]), "=r"(d[3]) : "r"(addr));
}

__device__ __forceinline__ void cpasync16(unsigned dst, const void* src)
{
    asm volatile("cp.async.cg.shared.global [%0], [%1], 16;" :: "r"(dst), "l"(src));
}
__device__ __forceinline__ void cpcommit()
{
    asm volatile("cp.async.commit_group;" ::: "memory");
}
template<int N>
__device__ __forceinline__ void cpwait()
{
    asm volatile("cp.async.wait_group %0;" :: "n"(N) : "memory");
}

// ---------------- pre-split kernels ----------------
__global__ __launch_bounds__(256) void split_x_kernel(
    const float* __restrict__ x, __half* __restrict__ oh, __half* __restrict__ ol)
{
    const size_t e = ((size_t)blockIdx.x * 256 + threadIdx.x) * 4;
    if (e >= (size_t)MTOK * HD) return;
    split8(oh + e, ol + e, *(const float4*)(x + e));
}

__global__ __launch_bounds__(256) void split_w_kernel(
    const float* __restrict__ wq, const float* __restrict__ wk, const float* __restrict__ wv,
    const float* __restrict__ wo, const float* __restrict__ f1, const float* __restrict__ f2,
    __half* __restrict__ oh)
{
    const size_t e = ((size_t)blockIdx.x * 256 + threadIdx.x) * 4;
    if (e >= (size_t)WTOT) return;
    const float* src; size_t off;
    if      (e < WOFF_K)  { src = wq; off = WOFF_Q;  }
    else if (e < WOFF_V)  { src = wk; off = WOFF_K;  }
    else if (e < WOFF_O)  { src = wv; off = WOFF_V;  }
    else if (e < WOFF_F1) { src = wo; off = WOFF_O;  }
    else if (e < WOFF_F2) { src = f1; off = WOFF_F1; }
    else                  { src = f2; off = WOFF_F2; }
    pack8hi(oh + e, *(const float4*)(src + (e - off)));
}

// =================================================================
// fp16 GEMM: B (weights) fp16 hi-only; A split or hi-only.
// MODE bit0=relu, bit1=fp16 out, bit2=suppress lo out, bit3=A hi-only.
// =================================================================
#define ASTR 40
#define BOFF (2*2*128*ASTR)
#define GEMM_SMEM ((2*2 + 2)*128*ASTR*2)   // 61440 B

template<int MODE>
__device__ __forceinline__ void gemm_core(
    const __half* __restrict__ Ah, const __half* __restrict__ Al,
    const __half* __restrict__ Bh,
    const float* __restrict__ bias, float* __restrict__ C,
    __half* __restrict__ Chi, __half* __restrict__ Clo,
    int N, int K, int m0, int n0)
{
    extern __shared__ __half sm_bf[];
    const unsigned sbase = (unsigned)__cvta_generic_to_shared(sm_bf);

    const int tid  = threadIdx.x;
    const int lane = tid & 31, warp = tid >> 5;
    const int wm = (warp >> 2) << 6;
    const int wn = (warp & 3)  << 5;
    const int g = lane >> 2, t = lane & 3;
    const int KT = K >> 5;

    const __half* Agh = Ah + (size_t)m0 * K;
    const __half* Agl = (MODE & 8) ? nullptr : (Al + (size_t)m0 * K);
    const __half* Bgh = Bh + (size_t)n0 * K;

    const int sr = tid >> 2;
    const int scol = (tid & 3) << 3;

    float acc[4][4][4];
    #pragma unroll
    for (int i = 0; i < 4; i++)
        #pragma unroll
        for (int j = 0; j < 4; j++)
            #pragma unroll
            for (int q = 0; q < 4; q++) acc[i][j][q] = 0.f;

    const int arow = lane & 15;
    const int acol = (lane >> 4) << 3;
    const int brow = (lane & 7) | ((lane >> 1) & 8);
    const int bcol = lane & 8;

    {
        #pragma unroll
        for (int i = 0; i < 2; i++) {
            const int r = (i << 6) + sr;
            cpasync16(sbase + (unsigned)(((0*2 + 0)*128 + r)*ASTR + scol) * 2,
                      Agh + (size_t)r * K + scol);
            if (!(MODE & 8))
                cpasync16(sbase + (unsigned)(((0*2 + 1)*128 + r)*ASTR + scol) * 2,
                          Agl + (size_t)r * K + scol);
            cpasync16(sbase + (unsigned)((BOFF + (0*128 + r)*ASTR + scol)) * 2,
                      Bgh + (size_t)r * K + scol);
        }
        cpcommit();
    }

    for (int kt = 0; kt < KT; kt++) {
        const int buf = kt & 1;
        if (kt + 1 < KT) {
            const int ko = (kt + 1) << 5;
            const int nb = buf ^ 1;
            #pragma unroll
            for (int i = 0; i < 2; i++) {
                const int r = (i << 6) + sr;
                cpasync16(sbase + (unsigned)(((nb*2 + 0)*128 + r)*ASTR + scol) * 2,
                          Agh + (size_t)r * K + ko + scol);
                if (!(MODE & 8))
                    cpasync16(sbase + (unsigned)(((nb*2 + 1)*128 + r)*ASTR + scol) * 2,
                              Agl + (size_t)r * K + ko + scol);
                cpasync16(sbase + (unsigned)((BOFF + (nb*128 + r)*ASTR + scol)) * 2,
                          Bgh + (size_t)r * K + ko + scol);
            }
            cpcommit();
            cpwait<1>();
        } else {
            cpwait<0>();
        }
        __syncthreads();

        const unsigned aHi = sbase + (unsigned)((buf*2 + 0)*128*ASTR) * 2;
        const unsigned aLo = sbase + (unsigned)((buf*2 + 1)*128*ASTR) * 2;
        const unsigned bHi = sbase + (unsigned)((BOFF + buf*128*ASTR)) * 2;

        #pragma unroll
        for (int ks = 0; ks < 2; ks++) {
            const int kc = ks << 4;
            unsigned bh[2][4];
            #pragma unroll
            for (int np = 0; np < 2; np++) {
                const unsigned bo = (unsigned)((wn + (np << 4) + brow)*ASTR + kc + bcol) * 2;
                ldsm4(bh[np], bHi + bo);
            }
            #pragma unroll
            for (int mh = 0; mh < 2; mh++) {
                unsigned ah[2][4], al[2][4];
                #pragma unroll
                for (int m2 = 0; m2 < 2; m2++) {
                    const unsigned ao = (unsigned)((wm + ((mh*2 + m2) << 4) + arow)*ASTR + kc + acol) * 2;
                    ldsm4(ah[m2], aHi + ao);
                    if (!(MODE & 8)) ldsm4(al[m2], aLo + ao);
                }
                #pragma unroll
                for (int m2 = 0; m2 < 2; m2++) {
                    #pragma unroll
                    for (int nt = 0; nt < 4; nt++)
                        mma16816(acc[mh*2 + m2][nt], ah[m2], bh[nt >> 1] + ((nt & 1) << 1));
                    if (!(MODE & 8)) {
                        #pragma unroll
                        for (int nt = 0; nt < 4; nt++)
                            mma16816(acc[mh*2 + m2][nt], al[m2], bh[nt >> 1] + ((nt & 1) << 1));
                    }
                }
            }
        }
        __syncthreads();
    }

    #pragma unroll
    for (int mt = 0; mt < 4; mt++) {
        const int row = m0 + wm + (mt << 4) + g;
        #pragma unroll
        for (int nt = 0; nt < 4; nt++) {
            const int col = n0 + wn + (nt << 3) + (t << 1);
            float bx = 0.f, by = 0.f;
            if (bias) { bx = bias[col]; by = bias[col + 1]; }
            float v0 = acc[mt][nt][0] + bx, v1 = acc[mt][nt][1] + by;
            float v2 = acc[mt][nt][2] + bx, v3 = acc[mt][nt][3] + by;
            if (MODE & 1) {
                v0 = fmaxf(v0, 0.f); v1 = fmaxf(v1, 0.f);
                v2 = fmaxf(v2, 0.f); v3 = fmaxf(v3, 0.f);
            }
            if (MODE & 2) {
                if (MODE & 4) {
                    *(unsigned*)(Chi + (size_t)row * N + col)       = packhi(v0, v1);
                    *(unsigned*)(Chi + (size_t)(row + 8) * N + col) = packhi(v2, v3);
                } else {
                    unsigned h01, l01, h23, l23;
                    packsplit(v0, v1, h01, l01);
                    packsplit(v2, v3, h23, l23);
                    *(unsigned*)(Chi + (size_t)row * N + col)       = h01;
                    *(unsigned*)(Chi + (size_t)(row + 8) * N + col) = h23;
                    *(unsigned*)(Clo + (size_t)row * N + col)       = l01;
                    *(unsigned*)(Clo + (size_t)(row + 8) * N + col) = l23;
                }
            } else {
                *(float2*)(C + (size_t)row * N + col)       = make_float2(v0, v1);
                *(float2*)(C + (size_t)(row + 8) * N + col) = make_float2(v2, v3);
            }
        }
    }
}

template<int MODE>
__global__ __launch_bounds__(256, 2) void gemm_kernel(
    const __half* __restrict__ Ah, const __half* __restrict__ Al,
    const __half* __restrict__ Bh,
    const float* __restrict__ bias, float* __restrict__ C,
    __half* __restrict__ Chi, __half* __restrict__ Clo, int N, int K)
{
    gemm_core<MODE>(Ah, Al, Bh, bias, C, Chi, Clo, N, K,
                    blockIdx.y << 7, blockIdx.x << 7);
}

// QKV: A = x split; outputs fp16 hi-only
__global__ __launch_bounds__(256, 2) void gemm_qkv_kernel(
    const __half* __restrict__ xh, const __half* __restrict__ xl,
    const __half* __restrict__ wh,
    __half* __restrict__ qh, __half* __restrict__ kh, __half* __restrict__ vh)
{
    const int z = blockIdx.z;
    const int mat = z >> 2, h = z & 3;
    const size_t woff = (size_t)mat * 262144 + (size_t)h * 65536;
    __half* Chi = (mat == 0 ? qh : mat == 1 ? kh : vh) + (size_t)h * MTOK * HD;
    gemm_core<6>(xh, xl, wh + woff, nullptr, nullptr,
                 Chi, nullptr, HD, HD, blockIdx.y << 7, blockIdx.x << 7);
}

// =================================================================
// flash v8: pure fp16 Q,K,V,P. 128 q-rows/CTA, 32-key tiles, 8 warps.
// Per-tile mma: QK 64, PV 64 (half of v7).
// =================================================================
#define QS 264
#define FLASH_SMEM ((128 + 2*32)*QS*2)   // 101376 B
#define L2E 1.4426950408889634f

__global__ __launch_bounds__(256, 1) void flash_mma_kernel(
    const __half* __restrict__ qh, const __half* __restrict__ kh,
    const __half* __restrict__ vh, const int* __restrict__ amask,
    __half* __restrict__ atth)
{
    extern __shared__ __half sm[];
    __half* sQh = sm;
    __half* sKh = sQh + 128*QS;
    __half* sVh = sKh + 32*QS;
    __shared__ int sMq[128];
    __shared__ int sMk[32];

    const int tid  = threadIdx.x;
    const int lane = tid & 31, w = tid >> 5;
    const int g = lane >> 2, t = lane & 3;
    const int bh = blockIdx.y;
    const int b = bh >> 2, h = bh & 3;
    const int qidx = (int)gridDim.x - 1 - (int)blockIdx.x;   // heavy first
    const int m0 = qidx << 7;
    const size_t base = ((size_t)h * MTOK + (size_t)b * SEQ) * HD;

    const unsigned bQh = (unsigned)__cvta_generic_to_shared(sQh);
    const unsigned bKh = (unsigned)__cvta_generic_to_shared(sKh);
    const unsigned bVh = (unsigned)__cvta_generic_to_shared(sVh);

    const unsigned offA = (((w << 4) + (lane & 15)) * QS + ((lane >> 4) << 3)) * 2;
    const unsigned offB = ((((lane & 7) | ((lane >> 1) & 8)) * QS) + (lane & 8)) * 2;
    const unsigned offV = (((lane & 15) * QS) + ((lane >> 4) << 3)) * 2;

    // ---- Q fill via cp.async ----
    {
        const __half* Qh = qh + base + (size_t)m0 * HD;
        for (int i = tid; i < 4096; i += 256) {
            int r = i >> 5, c = (i & 31) << 3;
            cpasync16(bQh + (unsigned)(r*QS + c)*2, Qh + (size_t)r*HD + c);
        }
        if (tid < 128) sMq[tid] = amask[b * SEQ + m0 + tid];
    }

    float accO[32][4];
    #pragma unroll
    for (int i = 0; i < 32; i++)
        #pragma unroll
        for (int j = 0; j < 4; j++) accO[i][j] = 0.f;
    float m_run0 = -1e30f, m_run1 = -1e30f, l_run0 = 0.f, l_run1 = 0.f;

    const int gi0 = m0 + (w << 4) + g;
    const int gi1 = gi0 + 8;

    const int ntiles = (qidx + 1) << 2;
    for (int kt = 0; kt < ntiles; kt++) {
        const int j0 = kt << 5;
        __syncthreads();
        {
            const __half* Kh = kh + base + (size_t)j0 * HD;
            const __half* Vh = vh + base + (size_t)j0 * HD;
            for (int i = tid; i < 1024; i += 256) {
                int r = i >> 5, c = (i & 31) << 3;
                const unsigned so = (unsigned)(r*QS + c) * 2;
                const size_t go = (size_t)r*HD + c;
                cpasync16(bKh + so, Kh + go);
                cpasync16(bVh + so, Vh + go);
            }
            if (tid < 32) sMk[tid] = amask[b * SEQ + j0 + tid];
            cpcommit();
            cpwait<0>();
        }
        __syncthreads();

        // ---- scores: Qh·Kh, 16 rows x 32 keys per warp ----
        float sc[4][4];
        #pragma unroll
        for (int i = 0; i < 4; i++)
            #pragma unroll
            for (int j = 0; j < 4; j++) sc[i][j] = 0.f;

        #pragma unroll 4
        for (int ks = 0; ks < 16; ks++) {
            unsigned aqh[4];
            ldsm4(aqh, bQh + offA + ks*32);
            #pragma unroll
            for (int p = 0; p < 2; p++) {
                unsigned kbh[4];
                ldsm4(kbh, bKh + offB + p*(16*QS*2) + ks*32);
                mma16816(sc[2*p],   aqh, kbh);
                mma16816(sc[2*p+1], aqh, kbh+2);
            }
        }

        // ---- mask + online softmax ----
        const int qm0 = sMq[(w << 4) + g];
        const int qm1 = sMq[(w << 4) + g + 8];
        float mx0 = -1e30f, mx1 = -1e30f;
        #pragma unroll
        for (int nt = 0; nt < 4; nt++) {
            const int jb = (nt << 3) + (t << 1);
            const int k0 = sMk[jb], k1 = sMk[jb + 1];
            const int gj0 = j0 + jb, gj1 = gj0 + 1;
            sc[nt][0] = (qm0 && k0 && gj0 <= gi0) ? sc[nt][0] * 0.0625f : -1e30f;
            sc[nt][1] = (qm0 && k1 && gj1 <= gi0) ? sc[nt][1] * 0.0625f : -1e30f;
            sc[nt][2] = (qm1 && k0 && gj0 <= gi1) ? sc[nt][2] * 0.0625f : -1e30f;
            sc[nt][3] = (qm1 && k1 && gj1 <= gi1) ? sc[nt][3] * 0.0625f : -1e30f;
            mx0 = fmaxf(mx0, fmaxf(sc[nt][0], sc[nt][1]));
            mx1 = fmaxf(mx1, fmaxf(sc[nt][2], sc[nt][3]));
        }
        mx0 = fmaxf(mx0, __shfl_xor_sync(0xffffffffu, mx0, 1, 4));
        mx0 = fmaxf(mx0, __shfl_xor_sync(0xffffffffu, mx0, 2, 4));
        mx1 = fmaxf(mx1, __shfl_xor_sync(0xffffffffu, mx1, 1, 4));
        mx1 = fmaxf(mx1, __shfl_xor_sync(0xffffffffu, mx1, 2, 4));

        const float mn0 = fmaxf(m_run0, mx0);
        const float mn1 = fmaxf(m_run1, mx1);
        const float al0 = exp2f((m_run0 - mn0) * L2E);
        const float al1 = exp2f((m_run1 - mn1) * L2E);
        m_run0 = mn0; m_run1 = mn1;

        float ps0 = 0.f, ps1 = 0.f;
        #pragma unroll
        for (int nt = 0; nt < 4; nt++) {
            float p0 = exp2f((sc[nt][0] - mn0) * L2E);
            float p1 = exp2f((sc[nt][1] - mn0) * L2E);
            float p2 = exp2f((sc[nt][2] - mn1) * L2E);
            float p3 = exp2f((sc[nt][3] - mn1) * L2E);
            sc[nt][0] = p0; sc[nt][1] = p1; sc[nt][2] = p2; sc[nt][3] = p3;
            ps0 += p0 + p1; ps1 += p2 + p3;
        }
        ps0 += __shfl_xor_sync(0xffffffffu, ps0, 1, 4);
        ps0 += __shfl_xor_sync(0xffffffffu, ps0, 2, 4);
        ps1 += __shfl_xor_sync(0xffffffffu, ps1, 1, 4);
        ps1 += __shfl_xor_sync(0xffffffffu, ps1, 2, 4);
        l_run0 = l_run0 * al0 + ps0;
        l_run1 = l_run1 * al1 + ps1;

        const bool skip = __all_sync(0xffffffffu, (al0 == 1.f) && (al1 == 1.f));
        if (!skip) {
            #pragma unroll
            for (int i = 0; i < 32; i++) {
                accO[i][0] *= al0; accO[i][1] *= al0;
                accO[i][2] *= al1; accO[i][3] *= al1;
            }
        }

        // ---- O += Ph·Vh ----
        #pragma unroll
        for (int ks = 0; ks < 2; ks++) {
            unsigned aPh[4];
            aPh[0] = packhi(sc[2*ks][0],   sc[2*ks][1]);
            aPh[1] = packhi(sc[2*ks][2],   sc[2*ks][3]);
            aPh[2] = packhi(sc[2*ks+1][0], sc[2*ks+1][1]);
            aPh[3] = packhi(sc[2*ks+1][2], sc[2*ks+1][3]);
            #pragma unroll
            for (int nv = 0; nv < 16; nv++) {
                unsigned vbh[4];
                ldsm4t(vbh, bVh + offV + ks*(16*QS*2) + nv*32);
                mma16816(accO[2*nv],   aPh, vbh);
                mma16816(accO[2*nv+1], aPh, vbh+2);
            }
        }
    }

    // ---- epilogue: fp16 hi-only store ----
    const int qm0 = sMq[(w << 4) + g];
    const int qm1 = sMq[(w << 4) + g + 8];
    const float inv0 = (qm0 && l_run0 > 0.f) ? (1.f / l_run0) : 0.f;
    const float inv1 = (qm1 && l_run1 > 0.f) ? (1.f / l_run1) : 0.f;
    const size_t o0 = (size_t)(b * SEQ + gi0) * (NH * HD) + h * HD;
    const size_t o1 = (size_t)(b * SEQ + gi1) * (NH * HD) + h * HD;
    #pragma unroll
    for (int nt = 0; nt < 32; nt++) {
        const int col = (nt << 3) + (t << 1);
        *(unsigned*)(atth + o0 + col) = packhi(accO[nt][0] * inv0, accO[nt][1] * inv0);
        *(unsigned*)(atth + o1 + col) = packhi(accO[nt][2] * inv1, accO[nt][3] * inv1);
    }
}

// ---------------- fused residual-add + LayerNorm ----------------
template<int SPLIT>
__global__ __launch_bounds__(256) void add_ln_kernel(
    const float* __restrict__ a, const float* __restrict__ b2,
    const float* __restrict__ g, const float* __restrict__ be,
    float* __restrict__ out,
    __half* __restrict__ oh, __half* __restrict__ ol)
{
    __shared__ float red[16];
    const int row = blockIdx.x, t = threadIdx.x;
    const size_t off = (size_t)row * HD + t;
    const float v = a[off] + b2[off];
    float sv = v, sq = v * v;
    #pragma unroll
    for (int o = 16; o; o >>= 1) {
        sv += __shfl_xor_sync(0xffffffffu, sv, o);
        sq += __shfl_xor_sync(0xffffffffu, sq, o);
    }
    if ((t & 31) == 0) { red[t >> 5] = sv; red[8 + (t >> 5)] = sq; }
    __syncthreads();
    if (t == 0) {
        float s1 = 0.f, s2 = 0.f;
        #pragma unroll
        for (int i = 0; i < 8; i++) { s1 += red[i]; s2 += red[8 + i]; }
        red[0] = s1; red[8] = s2;
    }
    __syncthreads();
    const float mu  = red[0] * (1.f / 256.f);
    const float var = red[8] * (1.f / 256.f) - mu * mu;
    const float r = (v - mu) * rsqrtf(var + 1e-5f) * g[t] + be[t];
    out[off] = r;
    if (SPLIT) {
        __half hi = __float2half_rn(r);
        oh[off] = hi;
        ol[off] = __float2half_rn(r - __half2float(hi));
    }
}

// ---------------- launch ----------------
extern "C" void kernel_launch(void* const* d_in, const int* in_sizes, int n_in,
                              void* d_out, int out_size)
{
    const float* x    = (const float*)d_in[0];
    const int*   am   = (const int*  )d_in[1];
    const float* wq   = (const float*)d_in[2];
    const float* wk   = (const float*)d_in[3];
    const float* wv   = (const float*)d_in[4];
    const float* wo_w = (const float*)d_in[5];
    const float* wo_b = (const float*)d_in[6];
    const float* ln1g = (const float*)d_in[7];
    const float* ln1b = (const float*)d_in[8];
    const float* f1w  = (const float*)d_in[9];
    const float* f1b  = (const float*)d_in[10];
    const float* f2w  = (const float*)d_in[11];
    const float* f2b  = (const float*)d_in[12];
    const float* ln2g = (const float*)d_in[13];
    const float* ln2b = (const float*)d_in[14];
    float* out = (float*)d_out;
    (void)in_sizes; (void)n_in; (void)out_size;

    __half *pxh, *pxl, *pwh, *pqh, *pkh, *pvh;
    __half *path, *px1h, *px1l, *phh, *phl;
    float *px1, *pt1;
    cudaGetSymbolAddress((void**)&pxh, g_xh);
    cudaGetSymbolAddress((void**)&pxl, g_xl);
    cudaGetSymbolAddress((void**)&pwh, g_wh);
    cudaGetSymbolAddress((void**)&pqh, g_qh);
    cudaGetSymbolAddress((void**)&pkh, g_kh);
    cudaGetSymbolAddress((void**)&pvh, g_vh);
    cudaGetSymbolAddress((void**)&path, g_ath);
    cudaGetSymbolAddress((void**)&px1h, g_x1h);
    cudaGetSymbolAddress((void**)&px1l, g_x1l);
    cudaGetSymbolAddress((void**)&phh, g_hh);
    cudaGetSymbolAddress((void**)&phl, g_hl);
    cudaGetSymbolAddress((void**)&px1, g_x1);
    cudaGetSymbolAddress((void**)&pt1, g_t1);

    cudaFuncSetAttribute(gemm_qkv_kernel, cudaFuncAttributeMaxDynamicSharedMemorySize, GEMM_SMEM);
    cudaFuncSetAttribute(gemm_kernel<0>,  cudaFuncAttributeMaxDynamicSharedMemorySize, GEMM_SMEM);
    cudaFuncSetAttribute(gemm_kernel<3>,  cudaFuncAttributeMaxDynamicSharedMemorySize, GEMM_SMEM);
    cudaFuncSetAttribute(gemm_kernel<8>,  cudaFuncAttributeMaxDynamicSharedMemorySize, GEMM_SMEM);
    cudaFuncSetAttribute(flash_mma_kernel, cudaFuncAttributeMaxDynamicSharedMemorySize, FLASH_SMEM);

    // ---- pre-split x; weights fp16 hi-only ----
    split_x_kernel<<<MTOK*HD/1024, 256>>>(x, pxh, pxl);
    split_w_kernel<<<WTOT/1024, 256>>>(wq, wk, wv, wo_w, f1w, f2w, pwh);

    // ---- QKV projections (fp16 hi-only out) ----
    gemm_qkv_kernel<<<dim3(HD/128, MTOK/128, 12), 256, GEMM_SMEM>>>(
        pxh, pxl, pwh, pqh, pkh, pvh);

    // ---- causal flash attention (v8: pure fp16) ----
    flash_mma_kernel<<<dim3(SEQ/128, BATCH*NH), 256, FLASH_SMEM>>>(
        pqh, pkh, pvh, am, path);

    // ---- output projection (A hi-only) + residual/LN1 ----
    gemm_kernel<8><<<dim3(HD/128, MTOK/128), 256, GEMM_SMEM>>>(
        path, nullptr, pwh + WOFF_O, wo_b, pt1, nullptr, nullptr, HD, NH*HD);
    add_ln_kernel<1><<<MTOK, 256>>>(x, pt1, ln1g, ln1b, px1, px1h, px1l);

    // ---- FFN (A split) ----
    gemm_kernel<3><<<dim3(FF/128, MTOK/128), 256, GEMM_SMEM>>>(
        px1h, px1l, pwh + WOFF_F1, f1b, nullptr, phh, phl, FF, HD);
    gemm_kernel<0><<<dim3(HD/128, MTOK/128), 256, GEMM_SMEM>>>(
        phh, phl, pwh + WOFF_F2, f2b, pt1, nullptr, nullptr, HD, FF);
    add_ln_kernel<0><<<MTOK, 256>>>(px1, pt1, ln2g, ln2b, out, nullptr, nullptr);
}

// round 17
// speedup vs baseline: 2.1499x; 1.2079x over previous
#include <cuda_runtime.h>
#include <cuda_fp16.h>
#include <math.h>
#include <stdint.h>

// ---------------- problem constants ----------------
#define NH    4
#define HD    256
#define SEQ   1024
#define BATCH 8
#define MTOK  (BATCH*SEQ)
#define FF    1024

#define WOFF_Q  0
#define WOFF_K  262144
#define WOFF_V  524288
#define WOFF_O  786432
#define WOFF_F1 1048576
#define WOFF_F2 1310720
#define WTOT    1572864

// ---------------- scratch (pure fp16 world) ----------------
__device__ __align__(16) __half g_xh [(size_t)MTOK*HD];
__device__ __align__(16) __half g_wh [(size_t)WTOT];
__device__ __align__(16) __half g_qh [(size_t)NH*MTOK*HD];
__device__ __align__(16) __half g_kh [(size_t)NH*MTOK*HD];
__device__ __align__(16) __half g_vh [(size_t)NH*MTOK*HD];
__device__ __align__(16) __half g_ath[(size_t)MTOK*NH*HD];
__device__ __align__(16) __half g_x1h[(size_t)MTOK*HD];
__device__ __align__(16) __half g_hh [(size_t)MTOK*FF];
__device__ float g_x1 [(size_t)MTOK*HD];
__device__ float g_t1 [(size_t)MTOK*HD];

// ---------------- helpers ----------------
__device__ __forceinline__ unsigned packhi(float a, float b)
{
    __half2 h = __floats2half2_rn(a, b);
    return *reinterpret_cast<unsigned*>(&h);
}

__device__ __forceinline__ void pack8hi(__half* hi_p, float4 v)
{
    *reinterpret_cast<uint2*>(hi_p) = make_uint2(packhi(v.x, v.y), packhi(v.z, v.w));
}

__device__ __forceinline__ void mma16816(float* c, const unsigned* a, const unsigned* b)
{
    asm volatile(
        "mma.sync.aligned.m16n8k16.row.col.f32.f16.f16.f32 "
        "{%0,%1,%2,%3}, {%4,%5,%6,%7}, {%8,%9}, {%0,%1,%2,%3};\n"
        : "+f"(c[0]), "+f"(c[1]), "+f"(c[2]), "+f"(c[3])
        : "r"(a[0]), "r"(a[1]), "r"(a[2]), "r"(a[3]), "r"(b[0]), "r"(b[1]));
}

__device__ __forceinline__ void ldsm4(unsigned* d, unsigned addr)
{
    asm volatile("ldmatrix.sync.aligned.m8n8.x4.shared.b16 {%0,%1,%2,%3}, [%4];"
                 : "=r"(d[0]), "=r"(d[1]), "=r"(d[2]), "=r"(d[3]) : "r"(addr));
}

__device__ __forceinline__ void ldsm4t(unsigned* d, unsigned addr)
{
    asm volatile("ldmatrix.sync.aligned.m8n8.x4.trans.shared.b16 {%0,%1,%2,%3}, [%4];"
                 : "=r"(d[0]), "=r"(d[1]), "=r"(d[2]), "=r"(d[3]) : "r"(addr));
}

__device__ __forceinline__ void cpasync16(unsigned dst, const void* src)
{
    asm volatile("cp.async.cg.shared.global [%0], [%1], 16;" :: "r"(dst), "l"(src));
}
__device__ __forceinline__ void cpcommit()
{
    asm volatile("cp.async.commit_group;" ::: "memory");
}
template<int N>
__device__ __forceinline__ void cpwait()
{
    asm volatile("cp.async.wait_group %0;" :: "n"(N) : "memory");
}

// ---------------- pre-convert kernels ----------------
__global__ __launch_bounds__(256) void conv_x_kernel(
    const float* __restrict__ x, __half* __restrict__ oh)
{
    const size_t e = ((size_t)blockIdx.x * 256 + threadIdx.x) * 4;
    if (e >= (size_t)MTOK * HD) return;
    pack8hi(oh + e, *(const float4*)(x + e));
}

__global__ __launch_bounds__(256) void conv_w_kernel(
    const float* __restrict__ wq, const float* __restrict__ wk, const float* __restrict__ wv,
    const float* __restrict__ wo, const float* __restrict__ f1, const float* __restrict__ f2,
    __half* __restrict__ oh)
{
    const size_t e = ((size_t)blockIdx.x * 256 + threadIdx.x) * 4;
    if (e >= (size_t)WTOT) return;
    const float* src; size_t off;
    if      (e < WOFF_K)  { src = wq; off = WOFF_Q;  }
    else if (e < WOFF_V)  { src = wk; off = WOFF_K;  }
    else if (e < WOFF_O)  { src = wv; off = WOFF_V;  }
    else if (e < WOFF_F1) { src = wo; off = WOFF_O;  }
    else if (e < WOFF_F2) { src = f1; off = WOFF_F1; }
    else                  { src = f2; off = WOFF_F2; }
    pack8hi(oh + e, *(const float4*)(src + (e - off)));
}

// =================================================================
// pure-fp16 GEMM: C = A[M,K]*B[N,K]^T, 1 mma product.
// MODE bit0=relu, bit1=fp16 out (else fp32 out).
// smem: A[buf][128][ASTR] + B[buf][128][ASTR]
// =================================================================
#define ASTR 40
#define BOFF (2*128*ASTR)
#define GEMM_SMEM (4*128*ASTR*2)   // 40960 B

template<int MODE>
__device__ __forceinline__ void gemm_core(
    const __half* __restrict__ Ah, const __half* __restrict__ Bh,
    const float* __restrict__ bias, float* __restrict__ C,
    __half* __restrict__ Chi,
    int N, int K, int m0, int n0)
{
    extern __shared__ __half sm_bf[];
    const unsigned sbase = (unsigned)__cvta_generic_to_shared(sm_bf);

    const int tid  = threadIdx.x;
    const int lane = tid & 31, warp = tid >> 5;
    const int wm = (warp >> 2) << 6;
    const int wn = (warp & 3)  << 5;
    const int g = lane >> 2, t = lane & 3;
    const int KT = K >> 5;

    const __half* Agh = Ah + (size_t)m0 * K;
    const __half* Bgh = Bh + (size_t)n0 * K;

    const int sr = tid >> 2;
    const int scol = (tid & 3) << 3;

    float acc[4][4][4];
    #pragma unroll
    for (int i = 0; i < 4; i++)
        #pragma unroll
        for (int j = 0; j < 4; j++)
            #pragma unroll
            for (int q = 0; q < 4; q++) acc[i][j][q] = 0.f;

    const int arow = lane & 15;
    const int acol = (lane >> 4) << 3;
    const int brow = (lane & 7) | ((lane >> 1) & 8);
    const int bcol = lane & 8;

    {
        #pragma unroll
        for (int i = 0; i < 2; i++) {
            const int r = (i << 6) + sr;
            cpasync16(sbase + (unsigned)((0*128 + r)*ASTR + scol) * 2,
                      Agh + (size_t)r * K + scol);
            cpasync16(sbase + (unsigned)((BOFF + (0*128 + r)*ASTR + scol)) * 2,
                      Bgh + (size_t)r * K + scol);
        }
        cpcommit();
    }

    for (int kt = 0; kt < KT; kt++) {
        const int buf = kt & 1;
        if (kt + 1 < KT) {
            const int ko = (kt + 1) << 5;
            const int nb = buf ^ 1;
            #pragma unroll
            for (int i = 0; i < 2; i++) {
                const int r = (i << 6) + sr;
                cpasync16(sbase + (unsigned)((nb*128 + r)*ASTR + scol) * 2,
                          Agh + (size_t)r * K + ko + scol);
                cpasync16(sbase + (unsigned)((BOFF + (nb*128 + r)*ASTR + scol)) * 2,
                          Bgh + (size_t)r * K + ko + scol);
            }
            cpcommit();
            cpwait<1>();
        } else {
            cpwait<0>();
        }
        __syncthreads();

        const unsigned aHi = sbase + (unsigned)(buf*128*ASTR) * 2;
        const unsigned bHi = sbase + (unsigned)((BOFF + buf*128*ASTR)) * 2;

        #pragma unroll
        for (int ks = 0; ks < 2; ks++) {
            const int kc = ks << 4;
            unsigned bh[2][4];
            #pragma unroll
            for (int np = 0; np < 2; np++) {
                const unsigned bo = (unsigned)((wn + (np << 4) + brow)*ASTR + kc + bcol) * 2;
                ldsm4(bh[np], bHi + bo);
            }
            #pragma unroll
            for (int mh = 0; mh < 2; mh++) {
                unsigned ah[2][4];
                #pragma unroll
                for (int m2 = 0; m2 < 2; m2++) {
                    const unsigned ao = (unsigned)((wm + ((mh*2 + m2) << 4) + arow)*ASTR + kc + acol) * 2;
                    ldsm4(ah[m2], aHi + ao);
                }
                #pragma unroll
                for (int m2 = 0; m2 < 2; m2++)
                    #pragma unroll
                    for (int nt = 0; nt < 4; nt++)
                        mma16816(acc[mh*2 + m2][nt], ah[m2], bh[nt >> 1] + ((nt & 1) << 1));
            }
        }
        __syncthreads();
    }

    #pragma unroll
    for (int mt = 0; mt < 4; mt++) {
        const int row = m0 + wm + (mt << 4) + g;
        #pragma unroll
        for (int nt = 0; nt < 4; nt++) {
            const int col = n0 + wn + (nt << 3) + (t << 1);
            float bx = 0.f, by = 0.f;
            if (bias) { bx = bias[col]; by = bias[col + 1]; }
            float v0 = acc[mt][nt][0] + bx, v1 = acc[mt][nt][1] + by;
            float v2 = acc[mt][nt][2] + bx, v3 = acc[mt][nt][3] + by;
            if (MODE & 1) {
                v0 = fmaxf(v0, 0.f); v1 = fmaxf(v1, 0.f);
                v2 = fmaxf(v2, 0.f); v3 = fmaxf(v3, 0.f);
            }
            if (MODE & 2) {
                *(unsigned*)(Chi + (size_t)row * N + col)       = packhi(v0, v1);
                *(unsigned*)(Chi + (size_t)(row + 8) * N + col) = packhi(v2, v3);
            } else {
                *(float2*)(C + (size_t)row * N + col)       = make_float2(v0, v1);
                *(float2*)(C + (size_t)(row + 8) * N + col) = make_float2(v2, v3);
            }
        }
    }
}

template<int MODE>
__global__ __launch_bounds__(256, 2) void gemm_kernel(
    const __half* __restrict__ Ah, const __half* __restrict__ Bh,
    const float* __restrict__ bias, float* __restrict__ C,
    __half* __restrict__ Chi, int N, int K)
{
    gemm_core<MODE>(Ah, Bh, bias, C, Chi, N, K,
                    blockIdx.y << 7, blockIdx.x << 7);
}

// batched QKV: fp16 in, fp16 out
__global__ __launch_bounds__(256, 2) void gemm_qkv_kernel(
    const __half* __restrict__ xh, const __half* __restrict__ wh,
    __half* __restrict__ qh, __half* __restrict__ kh, __half* __restrict__ vh)
{
    const int z = blockIdx.z;
    const int mat = z >> 2, h = z & 3;
    const size_t woff = (size_t)mat * 262144 + (size_t)h * 65536;
    __half* Chi = (mat == 0 ? qh : mat == 1 ? kh : vh) + (size_t)h * MTOK * HD;
    gemm_core<2>(xh, wh + woff, nullptr, nullptr, Chi, HD, HD,
                 blockIdx.y << 7, blockIdx.x << 7);
}

// =================================================================
// flash v8 (unchanged R16 winner): pure fp16, 128 q-rows, 32-key tiles.
// =================================================================
#define QS 264
#define FLASH_SMEM ((128 + 2*32)*QS*2)   // 101376 B
#define L2E 1.4426950408889634f

__global__ __launch_bounds__(256, 1) void flash_mma_kernel(
    const __half* __restrict__ qh, const __half* __restrict__ kh,
    const __half* __restrict__ vh, const int* __restrict__ amask,
    __half* __restrict__ atth)
{
    extern __shared__ __half sm[];
    __half* sQh = sm;
    __half* sKh = sQh + 128*QS;
    __half* sVh = sKh + 32*QS;
    __shared__ int sMq[128];
    __shared__ int sMk[32];

    const int tid  = threadIdx.x;
    const int lane = tid & 31, w = tid >> 5;
    const int g = lane >> 2, t = lane & 3;
    const int bh = blockIdx.y;
    const int b = bh >> 2, h = bh & 3;
    const int qidx = (int)gridDim.x - 1 - (int)blockIdx.x;
    const int m0 = qidx << 7;
    const size_t base = ((size_t)h * MTOK + (size_t)b * SEQ) * HD;

    const unsigned bQh = (unsigned)__cvta_generic_to_shared(sQh);
    const unsigned bKh = (unsigned)__cvta_generic_to_shared(sKh);
    const unsigned bVh = (unsigned)__cvta_generic_to_shared(sVh);

    const unsigned offA = (((w << 4) + (lane & 15)) * QS + ((lane >> 4) << 3)) * 2;
    const unsigned offB = ((((lane & 7) | ((lane >> 1) & 8)) * QS) + (lane & 8)) * 2;
    const unsigned offV = (((lane & 15) * QS) + ((lane >> 4) << 3)) * 2;

    {
        const __half* Qh = qh + base + (size_t)m0 * HD;
        for (int i = tid; i < 4096; i += 256) {
            int r = i >> 5, c = (i & 31) << 3;
            cpasync16(bQh + (unsigned)(r*QS + c)*2, Qh + (size_t)r*HD + c);
        }
        if (tid < 128) sMq[tid] = amask[b * SEQ + m0 + tid];
    }

    float accO[32][4];
    #pragma unroll
    for (int i = 0; i < 32; i++)
        #pragma unroll
        for (int j = 0; j < 4; j++) accO[i][j] = 0.f;
    float m_run0 = -1e30f, m_run1 = -1e30f, l_run0 = 0.f, l_run1 = 0.f;

    const int gi0 = m0 + (w << 4) + g;
    const int gi1 = gi0 + 8;

    const int ntiles = (qidx + 1) << 2;
    for (int kt = 0; kt < ntiles; kt++) {
        const int j0 = kt << 5;
        __syncthreads();
        {
            const __half* Kh = kh + base + (size_t)j0 * HD;
            const __half* Vh = vh + base + (size_t)j0 * HD;
            for (int i = tid; i < 1024; i += 256) {
                int r = i >> 5, c = (i & 31) << 3;
                const unsigned so = (unsigned)(r*QS + c) * 2;
                const size_t go = (size_t)r*HD + c;
                cpasync16(bKh + so, Kh + go);
                cpasync16(bVh + so, Vh + go);
            }
            if (tid < 32) sMk[tid] = amask[b * SEQ + j0 + tid];
            cpcommit();
            cpwait<0>();
        }
        __syncthreads();

        float sc[4][4];
        #pragma unroll
        for (int i = 0; i < 4; i++)
            #pragma unroll
            for (int j = 0; j < 4; j++) sc[i][j] = 0.f;

        #pragma unroll 4
        for (int ks = 0; ks < 16; ks++) {
            unsigned aqh[4];
            ldsm4(aqh, bQh + offA + ks*32);
            #pragma unroll
            for (int p = 0; p < 2; p++) {
                unsigned kbh[4];
                ldsm4(kbh, bKh + offB + p*(16*QS*2) + ks*32);
                mma16816(sc[2*p],   aqh, kbh);
                mma16816(sc[2*p+1], aqh, kbh+2);
            }
        }

        const int qm0 = sMq[(w << 4) + g];
        const int qm1 = sMq[(w << 4) + g + 8];
        float mx0 = -1e30f, mx1 = -1e30f;
        #pragma unroll
        for (int nt = 0; nt < 4; nt++) {
            const int jb = (nt << 3) + (t << 1);
            const int k0 = sMk[jb], k1 = sMk[jb + 1];
            const int gj0 = j0 + jb, gj1 = gj0 + 1;
            sc[nt][0] = (qm0 && k0 && gj0 <= gi0) ? sc[nt][0] * 0.0625f : -1e30f;
            sc[nt][1] = (qm0 && k1 && gj1 <= gi0) ? sc[nt][1] * 0.0625f : -1e30f;
            sc[nt][2] = (qm1 && k0 && gj0 <= gi1) ? sc[nt][2] * 0.0625f : -1e30f;
            sc[nt][3] = (qm1 && k1 && gj1 <= gi1) ? sc[nt][3] * 0.0625f : -1e30f;
            mx0 = fmaxf(mx0, fmaxf(sc[nt][0], sc[nt][1]));
            mx1 = fmaxf(mx1, fmaxf(sc[nt][2], sc[nt][3]));
        }
        mx0 = fmaxf(mx0, __shfl_xor_sync(0xffffffffu, mx0, 1, 4));
        mx0 = fmaxf(mx0, __shfl_xor_sync(0xffffffffu, mx0, 2, 4));
        mx1 = fmaxf(mx1, __shfl_xor_sync(0xffffffffu, mx1, 1, 4));
        mx1 = fmaxf(mx1, __shfl_xor_sync(0xffffffffu, mx1, 2, 4));

        const float mn0 = fmaxf(m_run0, mx0);
        const float mn1 = fmaxf(m_run1, mx1);
        const float al0 = exp2f((m_run0 - mn0) * L2E);
        const float al1 = exp2f((m_run1 - mn1) * L2E);
        m_run0 = mn0; m_run1 = mn1;

        float ps0 = 0.f, ps1 = 0.f;
        #pragma unroll
        for (int nt = 0; nt < 4; nt++) {
            float p0 = exp2f((sc[nt][0] - mn0) * L2E);
            float p1 = exp2f((sc[nt][1] - mn0) * L2E);
            float p2 = exp2f((sc[nt][2] - mn1) * L2E);
            float p3 = exp2f((sc[nt][3] - mn1) * L2E);
            sc[nt][0] = p0; sc[nt][1] = p1; sc[nt][2] = p2; sc[nt][3] = p3;
            ps0 += p0 + p1; ps1 += p2 + p3;
        }
        ps0 += __shfl_xor_sync(0xffffffffu, ps0, 1, 4);
        ps0 += __shfl_xor_sync(0xffffffffu, ps0, 2, 4);
        ps1 += __shfl_xor_sync(0xffffffffu, ps1, 1, 4);
        ps1 += __shfl_xor_sync(0xffffffffu, ps1, 2, 4);
        l_run0 = l_run0 * al0 + ps0;
        l_run1 = l_run1 * al1 + ps1;

        const bool skip = __all_sync(0xffffffffu, (al0 == 1.f) && (al1 == 1.f));
        if (!skip) {
            #pragma unroll
            for (int i = 0; i < 32; i++) {
                accO[i][0] *= al0; accO[i][1] *= al0;
                accO[i][2] *= al1; accO[i][3] *= al1;
            }
        }

        #pragma unroll
        for (int ks = 0; ks < 2; ks++) {
            unsigned aPh[4];
            aPh[0] = packhi(sc[2*ks][0],   sc[2*ks][1]);
            aPh[1] = packhi(sc[2*ks][2],   sc[2*ks][3]);
            aPh[2] = packhi(sc[2*ks+1][0], sc[2*ks+1][1]);
            aPh[3] = packhi(sc[2*ks+1][2], sc[2*ks+1][3]);
            #pragma unroll
            for (int nv = 0; nv < 16; nv++) {
                unsigned vbh[4];
                ldsm4t(vbh, bVh + offV + ks*(16*QS*2) + nv*32);
                mma16816(accO[2*nv],   aPh, vbh);
                mma16816(accO[2*nv+1], aPh, vbh+2);
            }
        }
    }

    const int qm0 = sMq[(w << 4) + g];
    const int qm1 = sMq[(w << 4) + g + 8];
    const float inv0 = (qm0 && l_run0 > 0.f) ? (1.f / l_run0) : 0.f;
    const float inv1 = (qm1 && l_run1 > 0.f) ? (1.f / l_run1) : 0.f;
    const size_t o0 = (size_t)(b * SEQ + gi0) * (NH * HD) + h * HD;
    const size_t o1 = (size_t)(b * SEQ + gi1) * (NH * HD) + h * HD;
    #pragma unroll
    for (int nt = 0; nt < 32; nt++) {
        const int col = (nt << 3) + (t << 1);
        *(unsigned*)(atth + o0 + col) = packhi(accO[nt][0] * inv0, accO[nt][1] * inv0);
        *(unsigned*)(atth + o1 + col) = packhi(accO[nt][2] * inv1, accO[nt][3] * inv1);
    }
}

// ---------------- fused residual-add + LayerNorm ----------------
template<int EMIT16>
__global__ __launch_bounds__(256) void add_ln_kernel(
    const float* __restrict__ a, const float* __restrict__ b2,
    const float* __restrict__ g, const float* __restrict__ be,
    float* __restrict__ out, __half* __restrict__ oh)
{
    __shared__ float red[16];
    const int row = blockIdx.x, t = threadIdx.x;
    const size_t off = (size_t)row * HD + t;
    const float v = a[off] + b2[off];
    float sv = v, sq = v * v;
    #pragma unroll
    for (int o = 16; o; o >>= 1) {
        sv += __shfl_xor_sync(0xffffffffu, sv, o);
        sq += __shfl_xor_sync(0xffffffffu, sq, o);
    }
    if ((t & 31) == 0) { red[t >> 5] = sv; red[8 + (t >> 5)] = sq; }
    __syncthreads();
    if (t == 0) {
        float s1 = 0.f, s2 = 0.f;
        #pragma unroll
        for (int i = 0; i < 8; i++) { s1 += red[i]; s2 += red[8 + i]; }
        red[0] = s1; red[8] = s2;
    }
    __syncthreads();
    const float mu  = red[0] * (1.f / 256.f);
    const float var = red[8] * (1.f / 256.f) - mu * mu;
    const float r = (v - mu) * rsqrtf(var + 1e-5f) * g[t] + be[t];
    out[off] = r;
    if (EMIT16) oh[off] = __float2half_rn(r);
}

// ---------------- launch ----------------
extern "C" void kernel_launch(void* const* d_in, const int* in_sizes, int n_in,
                              void* d_out, int out_size)
{
    const float* x    = (const float*)d_in[0];
    const int*   am   = (const int*  )d_in[1];
    const float* wq   = (const float*)d_in[2];
    const float* wk   = (const float*)d_in[3];
    const float* wv   = (const float*)d_in[4];
    const float* wo_w = (const float*)d_in[5];
    const float* wo_b = (const float*)d_in[6];
    const float* ln1g = (const float*)d_in[7];
    const float* ln1b = (const float*)d_in[8];
    const float* f1w  = (const float*)d_in[9];
    const float* f1b  = (const float*)d_in[10];
    const float* f2w  = (const float*)d_in[11];
    const float* f2b  = (const float*)d_in[12];
    const float* ln2g = (const float*)d_in[13];
    const float* ln2b = (const float*)d_in[14];
    float* out = (float*)d_out;
    (void)in_sizes; (void)n_in; (void)out_size;

    __half *pxh, *pwh, *pqh, *pkh, *pvh, *path, *px1h, *phh;
    float *px1, *pt1;
    cudaGetSymbolAddress((void**)&pxh, g_xh);
    cudaGetSymbolAddress((void**)&pwh, g_wh);
    cudaGetSymbolAddress((void**)&pqh, g_qh);
    cudaGetSymbolAddress((void**)&pkh, g_kh);
    cudaGetSymbolAddress((void**)&pvh, g_vh);
    cudaGetSymbolAddress((void**)&path, g_ath);
    cudaGetSymbolAddress((void**)&px1h, g_x1h);
    cudaGetSymbolAddress((void**)&phh, g_hh);
    cudaGetSymbolAddress((void**)&px1, g_x1);
    cudaGetSymbolAddress((void**)&pt1, g_t1);

    cudaFuncSetAttribute(gemm_qkv_kernel, cudaFuncAttributeMaxDynamicSharedMemorySize, GEMM_SMEM);
    cudaFuncSetAttribute(gemm_kernel<0>,  cudaFuncAttributeMaxDynamicSharedMemorySize, GEMM_SMEM);
    cudaFuncSetAttribute(gemm_kernel<3>,  cudaFuncAttributeMaxDynamicSharedMemorySize, GEMM_SMEM);
    cudaFuncSetAttribute(flash_mma_kernel, cudaFuncAttributeMaxDynamicSharedMemorySize, FLASH_SMEM);

    // ---- convert x and weights to fp16 ----
    conv_x_kernel<<<MTOK*HD/1024, 256>>>(x, pxh);
    conv_w_kernel<<<WTOT/1024, 256>>>(wq, wk, wv, wo_w, f1w, f2w, pwh);

    // ---- QKV projections (pure fp16) ----
    gemm_qkv_kernel<<<dim3(HD/128, MTOK/128, 12), 256, GEMM_SMEM>>>(
        pxh, pwh, pqh, pkh, pvh);

    // ---- causal flash attention ----
    flash_mma_kernel<<<dim3(SEQ/128, BATCH*NH), 256, FLASH_SMEM>>>(
        pqh, pkh, pvh, am, path);

    // ---- output projection + residual/LN1 ----
    gemm_kernel<0><<<dim3(HD/128, MTOK/128), 256, GEMM_SMEM>>>(
        path, pwh + WOFF_O, wo_b, pt1, nullptr, HD, NH*HD);
    add_ln_kernel<1><<<MTOK, 256>>>(x, pt1, ln1g, ln1b, px1, px1h);

    // ---- FFN (pure fp16) ----
    gemm_kernel<3><<<dim3(FF/128, MTOK/128), 256, GEMM_SMEM>>>(
        px1h, pwh + WOFF_F1, f1b, nullptr, phh, FF, HD);
    gemm_kernel<0><<<dim3(HD/128, MTOK/128), 256, GEMM_SMEM>>>(
        phh, pwh + WOFF_F2, f2b, pt1, nullptr, HD, FF);
    add_ln_kernel<0><<<MTOK, 256>>>(px1, pt1, ln2g, ln2b, out, nullptr);
}